// round 11
// baseline (speedup 1.0000x reference)
#include <cuda_runtime.h>
#include <stdint.h>
#include <math.h>

#define NN 16000
#define EE 256000
#define EP (EE+NN)
#define DIN 1280
#define HD 256
#define GG 32
#define OO 64

// rounded-weight scratch layout (floats)
#define FPW_OFF   0
#define WL_OFF    327680
#define WR_OFF    458752
#define GINW_OFF  589824
#define RESW_OFF  720896
#define POOLW_OFF 851968
#define RW_TOT    917504

// dynamic smem for gemm: As[2][128][20] + Bs[2][16][264]
#define AS_FLOATS (2*128*20)
#define BS_FLOATS (2*16*264)
#define SMEM_SZ ((AS_FLOATS + BS_FLOATS)*4)

// ---------------- device scratch (static, allocation-free) ----------------
__device__ float d_h0[NN*HD];
__device__ float d_h1[NN*HD];
__device__ float d_xl[NN*HD];
__device__ float d_xr[NN*HD];
__device__ float d_rw[RW_TOT];
__device__ int   d_degGat[NN], d_degGin[NN];
__device__ int   d_ptrGat[NN+1], d_ptrGin[NN+1];
__device__ int   d_curGat[NN], d_curGin[NN];
__device__ int   d_colGat[EP], d_colGin[EE];
__device__ float d_red[4];
__device__ float d_gate[NN], d_gsum[GG], d_emb[GG*HD];

__device__ __forceinline__ void atomicMaxF(float* addr, float v){
  if (v >= 0.f) atomicMax((int*)addr, __float_as_int(v));
  else          atomicMin((unsigned int*)addr, __float_as_uint(v));
}

__device__ __forceinline__ uint32_t tf32u(float x){
  uint32_t u; asm("cvt.rna.tf32.f32 %0, %1;" : "=r"(u) : "f"(x));
  return u;
}

#define CP16(dst, src) asm volatile("cp.async.cg.shared.global [%0], [%1], 16;\n" :: "r"(dst), "l"(src))
#define CP_COMMIT()    asm volatile("cp.async.commit_group;\n" ::)
template<int N>
__device__ __forceinline__ void cp_wait(){ asm volatile("cp.async.wait_group %0;\n" :: "n"(N)); }

// ---------------- init + weight pre-round (fused; independent work) ----------------
__global__ void initro_kernel(int* degGat,int* degGin,float* red,float* emb,float* gate,
                              float* out, const float* __restrict__ head_b2,
                              const float* __restrict__ fpW, const float* __restrict__ wl,
                              const float* __restrict__ wr, const float* __restrict__ ginw,
                              const float* __restrict__ resw, const float* __restrict__ poolw,
                              float* __restrict__ rw){
  int i = blockIdx.x*blockDim.x+threadIdx.x;
  if (i < NN){ degGat[i]=0; degGin[i]=0; gate[i]=0.f; }
  if (i < 4)  red[i]=0.f;
  if (i < GG*HD) emb[i]=0.f;
  if (i < GG*OO) out[i] = head_b2[i % OO];
  for (int idx = i; idx < RW_TOT; idx += gridDim.x*blockDim.x){
    float v; int j = idx;
    if (j < 327680) v = fpW[j];
    else { j -= 327680;
      if (j < 131072) v = wl[j];
      else { j -= 131072;
        if (j < 131072) v = wr[j];
        else { j -= 131072;
          if (j < 131072) v = ginw[j];
          else { j -= 131072;
            if (j < 131072) v = resw[j];
            else v = poolw[j-131072];
          }
        }
      }
    }
    rw[idx] = __uint_as_float(tf32u(v));
  }
}

__global__ void hist_kernel(const int* __restrict__ ei, int* degGat, int* degGin){
  int e = blockIdx.x*blockDim.x+threadIdx.x;
  if (e >= EP) return;
  if (e < EE){
    int d = ei[EE+e];
    atomicAdd(&degGat[d],1);
    atomicAdd(&degGin[d],1);
  } else {
    atomicAdd(&degGat[e-EE],1);
  }
}

// shuffle-based scan: 2 blocks (GAT/GIN), 1024 threads, 16 elems/thread
__global__ void scan2_kernel(const int* __restrict__ degA, int* ptrA, int* curA,
                             const int* __restrict__ degB, int* ptrB, int* curB){
  const int* deg = blockIdx.x ? degB : degA;
  int* indptr    = blockIdx.x ? ptrB : ptrA;
  int* cursor    = blockIdx.x ? curB : curA;
  int t = threadIdx.x;
  int lane = t & 31, wid = t >> 5;
  const int CH = 16;
  int st = t*CH;
  int dv[CH];
  int mySum = 0;
  #pragma unroll
  for (int i=0;i<CH;i++){
    int idx = st+i;
    dv[i] = (idx<NN)? deg[idx] : 0;
    mySum += dv[i];
  }
  int inc = mySum;
  #pragma unroll
  for (int off=1; off<32; off<<=1){
    int n = __shfl_up_sync(0xffffffffu, inc, off);
    if (lane >= off) inc += n;
  }
  __shared__ int wtot[32];
  if (lane==31) wtot[wid] = inc;
  __syncthreads();
  if (wid==0){
    int v = wtot[lane];
    #pragma unroll
    for (int off=1; off<32; off<<=1){
      int n = __shfl_up_sync(0xffffffffu, v, off);
      if (lane >= off) v += n;
    }
    wtot[lane] = v;
  }
  __syncthreads();
  int run = inc - mySum + (wid>0 ? wtot[wid-1] : 0);
  #pragma unroll
  for (int i=0;i<CH;i++){
    int idx = st+i;
    if (idx<NN){ indptr[idx]=run; cursor[idx]=run; run+=dv[i]; }
  }
  if (t==1023) indptr[NN] = wtot[31];
}

__global__ void fill_kernel(const int* __restrict__ ei, int* curGat, int* colGat, int* curGin, int* colGin){
  int e = blockIdx.x*blockDim.x+threadIdx.x;
  if (e >= EP) return;
  if (e < EE){
    int s = ei[e], d = ei[EE+e];
    colGat[atomicAdd(&curGat[d],1)] = s;
    colGin[atomicAdd(&curGin[d],1)] = s;
  } else {
    int v = e-EE;
    colGat[atomicAdd(&curGat[v],1)] = v;
  }
}

// --- 128x256-tile tf32 GEMM, 8 warps of 64x64, 2-stage cp.async, fused epi ---
enum { EPI_BIAS=0, EPI_RELU_BN=1, EPI_GIN=2, EPI_RES=3, EPI_POOL=4 };

template<int EPI, bool DUAL>
__global__ __launch_bounds__(256)
void gemm_tc(const float* __restrict__ A,
             const float* __restrict__ B,  const float* __restrict__ bias,
             const float* __restrict__ B2, const float* __restrict__ bias2, float* __restrict__ C2,
             const float* __restrict__ g,   const float* __restrict__ be,
             const float* __restrict__ lng, const float* __restrict__ lnb,
             const float* __restrict__ hres,
             const float* __restrict__ stats, float* __restrict__ statsOut,
             const float* __restrict__ W2pool, float* __restrict__ gatebuf,
             float* __restrict__ C, int K)
{
  extern __shared__ float sm[];
  float* AsP = sm;
  float* BsP = sm + AS_FLOATS;
  int tid = threadIdx.x;
  int lane = tid & 31, w = tid >> 5;
  int warpM = (w >> 2) * 64;
  int warpN = (w & 3) * 64;
  int m0 = blockIdx.x * 128;
  const float* Bp = B; const float* biasp = bias; float* Cp = C;
  if (DUAL && blockIdx.y == 1){ Bp = B2; biasp = bias2; Cp = C2; }
  int tg = lane >> 2, tk = lane & 3;

  float acc[4][8][4];
  #pragma unroll
  for (int i=0;i<4;i++)
    #pragma unroll
    for (int j=0;j<8;j++)
      #pragma unroll
      for (int r=0;r<4;r++) acc[i][j][r]=0.f;

  int rowA  = tid >> 2;
  int k4A   = (tid & 3) * 4;
  int krB = tid >> 4;
  int nbB = (tid & 15)*4;

  uint32_t sA0[2], sA1[2], sB[2];
  #pragma unroll
  for (int s=0;s<2;s++){
    sA0[s] = (uint32_t)__cvta_generic_to_shared(&AsP[s*2560 + rowA*20 + k4A]);
    sA1[s] = (uint32_t)__cvta_generic_to_shared(&AsP[s*2560 + (rowA+64)*20 + k4A]);
    sB[s]  = (uint32_t)__cvta_generic_to_shared(&BsP[s*4224 + krB*264 + nbB]);
  }
  const float* gA0 = A  + (long)(m0+rowA   )*K + k4A;
  const float* gA1 = A  + (long)(m0+rowA+64)*K + k4A;
  const float* gB  = Bp + (long)krB*HD + nbB;

  int nk = K >> 4;
  CP16(sA0[0], gA0); CP16(sA1[0], gA1);
  #pragma unroll
  for (int c4=0;c4<4;c4++) CP16(sB[0] + c4*256, gB + c4*64);
  CP_COMMIT();

  for (int kt=0; kt<nk; kt++){
    int st = kt & 1;
    cp_wait<0>();
    __syncthreads();
    if (kt+1 < nk){
      int s2 = st ^ 1;
      int kb = (kt+1)<<4;
      CP16(sA0[s2], gA0+kb); CP16(sA1[s2], gA1+kb);
      const float* gBk = gB + (long)kb*HD;
      #pragma unroll
      for (int c4=0;c4<4;c4++) CP16(sB[s2] + c4*256, gBk + c4*64);
      CP_COMMIT();
    }
    const float* Abase = AsP + st*2560;
    const float* Bbase = BsP + st*4224;
    #pragma unroll
    for (int ks=0; ks<2; ks++){
      int k0 = ks*8;
      uint32_t a[4][4], b[8][2];
      #pragma unroll
      for (int i=0;i<4;i++){
        int r = warpM + i*16 + tg;
        a[i][0] = tf32u(Abase[(r  )*20 + k0+tk  ]);
        a[i][1] = tf32u(Abase[(r+8)*20 + k0+tk  ]);
        a[i][2] = tf32u(Abase[(r  )*20 + k0+tk+4]);
        a[i][3] = tf32u(Abase[(r+8)*20 + k0+tk+4]);
      }
      #pragma unroll
      for (int j=0;j<8;j++){
        int c = warpN + j*8 + tg;
        b[j][0] = __float_as_uint(Bbase[(k0+tk  )*264 + c]);
        b[j][1] = __float_as_uint(Bbase[(k0+tk+4)*264 + c]);
      }
      #pragma unroll
      for (int i=0;i<4;i++)
        #pragma unroll
        for (int j=0;j<8;j++)
          asm volatile("mma.sync.aligned.m16n8k8.row.col.f32.tf32.tf32.f32 "
            "{%0,%1,%2,%3}, {%4,%5,%6,%7}, {%8,%9}, {%0,%1,%2,%3};"
            : "+f"(acc[i][j][0]), "+f"(acc[i][j][1]),
              "+f"(acc[i][j][2]), "+f"(acc[i][j][3])
            : "r"(a[i][0]), "r"(a[i][1]), "r"(a[i][2]), "r"(a[i][3]),
              "r"(b[j][0]), "r"(b[j][1]));
    }
  }

  // ---- epilogue ----
  const float BNS = rsqrtf(1.0f + 1e-5f);
  float mean=0.f, rdenom=1.f;
  if (EPI==EPI_RES){
    const float inv = 1.0f/((float)NN*(float)HD);
    mean = stats[0]*inv;
    float var = stats[1]*inv - mean*mean;
    rdenom = 1.f/(sqrtf(fmaxf(var,0.f)) + 1e-5f);
  }
  float ssum=0.f, sq=0.f;
  float pgate[4][2];
  if (EPI==EPI_POOL){
    #pragma unroll
    for (int i=0;i<4;i++){ pgate[i][0]=0.f; pgate[i][1]=0.f; }
  }
  #pragma unroll
  for (int j=0;j<8;j++){
    int col = warpN + j*8 + tk*2;
    float b0 = biasp[col], b1 = biasp[col+1];
    float g0=0.f,g1=0.f,e0=0.f,e1=0.f;
    if (EPI==EPI_RELU_BN || EPI==EPI_GIN){
      g0=g[col]*BNS; g1=g[col+1]*BNS; e0=be[col]; e1=be[col+1];
    }
    float lg0=0.f,lg1=0.f,lb0=0.f,lb1=0.f;
    if (EPI==EPI_RES){
      lg0=lng[col]; lg1=lng[col+1]; lb0=lnb[col]; lb1=lnb[col+1];
    }
    float w20=0.f,w21=0.f;
    if (EPI==EPI_POOL){ w20=W2pool[col]; w21=W2pool[col+1]; }
    #pragma unroll
    for (int i=0;i<4;i++){
      #pragma unroll
      for (int h=0;h<2;h++){
        int row = m0 + warpM + i*16 + tg + h*8;
        float v0 = acc[i][j][h*2+0] + b0;
        float v1 = acc[i][j][h*2+1] + b1;
        if (EPI==EPI_RELU_BN){
          v0 = fmaxf(v0,0.f)*g0 + e0;
          v1 = fmaxf(v1,0.f)*g1 + e1;
        } else if (EPI==EPI_GIN){
          v0 = fmaxf(v0,0.f)*g0 + e0; v0 = (v0>0.f)? v0 : 0.2f*v0;
          v1 = fmaxf(v1,0.f)*g1 + e1; v1 = (v1>0.f)? v1 : 0.2f*v1;
          ssum += v0+v1; sq += v0*v0+v1*v1;
        } else if (EPI==EPI_RES){
          float2 hv = *(const float2*)&hres[(long)row*HD + col];
          v0 += (hv.x-mean)*rdenom*lg0 + lb0;
          v1 += (hv.y-mean)*rdenom*lg1 + lb1;
          v0 = (v0>0.f)? v0 : 0.2f*v0;
          v1 = (v1>0.f)? v1 : 0.2f*v1;
        } else if (EPI==EPI_POOL){
          pgate[i][h] += tanhf(v0)*w20 + tanhf(v1)*w21;
        }
        if (EPI!=EPI_POOL)
          *(float2*)&Cp[(long)row*HD + col] = make_float2(v0,v1);
      }
    }
  }
  if (EPI==EPI_GIN){
    #pragma unroll
    for (int off=16; off>0; off>>=1){
      ssum += __shfl_xor_sync(0xffffffffu, ssum, off);
      sq   += __shfl_xor_sync(0xffffffffu, sq,   off);
    }
    if (lane==0){
      atomicAdd(&statsOut[0], ssum);
      atomicAdd(&statsOut[1], sq);
    }
  }
  if (EPI==EPI_POOL){
    #pragma unroll
    for (int i=0;i<4;i++)
      #pragma unroll
      for (int h=0;h<2;h++){
        float p = pgate[i][h];
        p += __shfl_xor_sync(0xffffffffu, p, 1);
        p += __shfl_xor_sync(0xffffffffu, p, 2);
        if (tk==0){
          int row = m0 + warpM + i*16 + tg + h*8;
          atomicAdd(&gatebuf[row], p);
        }
      }
  }
}

// ------- GATv2: warp-per-node, float4 lanes, 2-edge unroll for MLP -------
__device__ __forceinline__ void gat_edge_logits(
    const float4& x0, const float4& x1,
    const float4& xr0, const float4& xr1,
    const float4& a0, const float4& a1,
    float& q0, float& q1)
{
  float v;
  v = x0.x+xr0.x; v = v>0.f?v:0.2f*v; q0  = v*a0.x;
  v = x0.y+xr0.y; v = v>0.f?v:0.2f*v; q0 += v*a0.y;
  v = x0.z+xr0.z; v = v>0.f?v:0.2f*v; q0 += v*a0.z;
  v = x0.w+xr0.w; v = v>0.f?v:0.2f*v; q0 += v*a0.w;
  v = x1.x+xr1.x; v = v>0.f?v:0.2f*v; q1  = v*a1.x;
  v = x1.y+xr1.y; v = v>0.f?v:0.2f*v; q1 += v*a1.y;
  v = x1.z+xr1.z; v = v>0.f?v:0.2f*v; q1 += v*a1.z;
  v = x1.w+xr1.w; v = v>0.f?v:0.2f*v; q1 += v*a1.w;
}

__global__ __launch_bounds__(256)
void gat_kernel(const float4* __restrict__ xl4, const float4* __restrict__ xr4,
                const int* __restrict__ indptr, const int* __restrict__ col,
                const float* __restrict__ att, const float* __restrict__ gbias,
                float* __restrict__ hout){
  int w = (blockIdx.x*blockDim.x + threadIdx.x)>>5;
  int lane = threadIdx.x & 31;
  if (w >= NN) return;
  const float4* at4 = (const float4*)att;
  float4 a0 = at4[lane], a1 = at4[32+lane];
  float4 xr0 = xr4[w*64 + lane], xr1 = xr4[w*64 + 32 + lane];
  float4 acc0 = make_float4(0,0,0,0), acc1 = make_float4(0,0,0,0);
  float s0=0.f, s1=0.f;
  int p0 = indptr[w], p1 = indptr[w+1];
  int j = p0;
  for (; j+1 < p1; j += 2){
    int ua = col[j], ub = col[j+1];
    float4 x0a = xl4[ua*64 + lane];
    float4 x1a = xl4[ua*64 + 32 + lane];
    float4 x0b = xl4[ub*64 + lane];
    float4 x1b = xl4[ub*64 + 32 + lane];
    float q0a,q1a,q0b,q1b;
    gat_edge_logits(x0a,x1a,xr0,xr1,a0,a1,q0a,q1a);
    gat_edge_logits(x0b,x1b,xr0,xr1,a0,a1,q0b,q1b);
    // interleaved shuffle chains (independent)
    q0a += __shfl_xor_sync(0xffffffffu,q0a,1);
    q1a += __shfl_xor_sync(0xffffffffu,q1a,1);
    q0b += __shfl_xor_sync(0xffffffffu,q0b,1);
    q1b += __shfl_xor_sync(0xffffffffu,q1b,1);
    q0a += __shfl_xor_sync(0xffffffffu,q0a,2);
    q1a += __shfl_xor_sync(0xffffffffu,q1a,2);
    q0b += __shfl_xor_sync(0xffffffffu,q0b,2);
    q1b += __shfl_xor_sync(0xffffffffu,q1b,2);
    q0a += __shfl_xor_sync(0xffffffffu,q0a,4);
    q1a += __shfl_xor_sync(0xffffffffu,q1a,4);
    q0b += __shfl_xor_sync(0xffffffffu,q0b,4);
    q1b += __shfl_xor_sync(0xffffffffu,q1b,4);
    float c0a = __expf(q0a), c1a = __expf(q1a);
    float c0b = __expf(q0b), c1b = __expf(q1b);
    // accumulate in original edge order (a then b)
    s0 += c0a; s1 += c1a;
    acc0.x += c0a*x0a.x; acc0.y += c0a*x0a.y; acc0.z += c0a*x0a.z; acc0.w += c0a*x0a.w;
    acc1.x += c1a*x1a.x; acc1.y += c1a*x1a.y; acc1.z += c1a*x1a.z; acc1.w += c1a*x1a.w;
    s0 += c0b; s1 += c1b;
    acc0.x += c0b*x0b.x; acc0.y += c0b*x0b.y; acc0.z += c0b*x0b.z; acc0.w += c0b*x0b.w;
    acc1.x += c1b*x1b.x; acc1.y += c1b*x1b.y; acc1.z += c1b*x1b.z; acc1.w += c1b*x1b.w;
  }
  if (j < p1){
    int u = col[j];
    float4 x0 = xl4[u*64 + lane];
    float4 x1 = xl4[u*64 + 32 + lane];
    float q0,q1;
    gat_edge_logits(x0,x1,xr0,xr1,a0,a1,q0,q1);
    q0 += __shfl_xor_sync(0xffffffffu,q0,1);
    q1 += __shfl_xor_sync(0xffffffffu,q1,1);
    q0 += __shfl_xor_sync(0xffffffffu,q0,2);
    q1 += __shfl_xor_sync(0xffffffffu,q1,2);
    q0 += __shfl_xor_sync(0xffffffffu,q0,4);
    q1 += __shfl_xor_sync(0xffffffffu,q1,4);
    float c0 = __expf(q0), c1 = __expf(q1);
    s0 += c0; s1 += c1;
    acc0.x += c0*x0.x; acc0.y += c0*x0.y; acc0.z += c0*x0.z; acc0.w += c0*x0.w;
    acc1.x += c1*x1.x; acc1.y += c1*x1.y; acc1.z += c1*x1.z; acc1.w += c1*x1.w;
  }
  float r0 = 1.f/(s0+1e-16f), r1 = 1.f/(s1+1e-16f);
  const float4* gb4 = (const float4*)gbias;
  float4 b0 = gb4[lane], b1 = gb4[32+lane];
  float4 o0, o1;
  o0.x=acc0.x*r0+b0.x; o0.y=acc0.y*r0+b0.y; o0.z=acc0.z*r0+b0.z; o0.w=acc0.w*r0+b0.w;
  o1.x=acc1.x*r1+b1.x; o1.y=acc1.y*r1+b1.y; o1.z=acc1.z*r1+b1.z; o1.w=acc1.w*r1+b1.w;
  ((float4*)hout)[w*64 + lane]      = o0;
  ((float4*)hout)[w*64 + 32 + lane] = o1;
}

// ---------------- GIN aggregation (float4, 4-edge unroll) ----------------
__global__ __launch_bounds__(256)
void ginagg_kernel(const float4* __restrict__ h4, const int* __restrict__ indptr,
                   const int* __restrict__ col, float* __restrict__ tmp){
  int w = (blockIdx.x*blockDim.x + threadIdx.x)>>5;
  int lane = threadIdx.x & 31;
  if (w >= NN) return;
  float4 acc0 = h4[w*64 + lane];
  float4 acc1 = h4[w*64 + 32 + lane];
  int p0 = indptr[w], p1 = indptr[w+1];
  int j = p0;
  for (; j+3 < p1; j += 4){
    int u0 = col[j], u1 = col[j+1], u2 = col[j+2], u3 = col[j+3];
    float4 x00 = h4[u0*64 + lane], x01 = h4[u0*64 + 32 + lane];
    float4 x10 = h4[u1*64 + lane], x11 = h4[u1*64 + 32 + lane];
    float4 x20 = h4[u2*64 + lane], x21 = h4[u2*64 + 32 + lane];
    float4 x30 = h4[u3*64 + lane], x31 = h4[u3*64 + 32 + lane];
    acc0.x+=x00.x; acc0.y+=x00.y; acc0.z+=x00.z; acc0.w+=x00.w;
    acc1.x+=x01.x; acc1.y+=x01.y; acc1.z+=x01.z; acc1.w+=x01.w;
    acc0.x+=x10.x; acc0.y+=x10.y; acc0.z+=x10.z; acc0.w+=x10.w;
    acc1.x+=x11.x; acc1.y+=x11.y; acc1.z+=x11.z; acc1.w+=x11.w;
    acc0.x+=x20.x; acc0.y+=x20.y; acc0.z+=x20.z; acc0.w+=x20.w;
    acc1.x+=x21.x; acc1.y+=x21.y; acc1.z+=x21.z; acc1.w+=x21.w;
    acc0.x+=x30.x; acc0.y+=x30.y; acc0.z+=x30.z; acc0.w+=x30.w;
    acc1.x+=x31.x; acc1.y+=x31.y; acc1.z+=x31.z; acc1.w+=x31.w;
  }
  for (; j < p1; j++){
    int u = col[j];
    float4 x0 = h4[u*64 + lane];
    float4 x1 = h4[u*64 + 32 + lane];
    acc0.x+=x0.x; acc0.y+=x0.y; acc0.z+=x0.z; acc0.w+=x0.w;
    acc1.x+=x1.x; acc1.y+=x1.y; acc1.z+=x1.z; acc1.w+=x1.w;
  }
  ((float4*)tmp)[w*64 + lane]      = acc0;
  ((float4*)tmp)[w*64 + 32 + lane] = acc1;
}

// ---------------- pooling: batch softmax (single block) ----------------
__global__ void bsoftmax_kernel(float* __restrict__ gate, const int* __restrict__ batch,
                                const float* __restrict__ b2, float* __restrict__ gsum){
  __shared__ float smax[GG], ssum[GG];
  int t = threadIdx.x;  // 1024 threads
  if (t < GG){ smax[t] = -1e30f; ssum[t] = 0.f; }
  __syncthreads();
  float b2v = b2[0];
  for (int v=t; v<NN; v+=1024)
    atomicMaxF(&smax[batch[v]], gate[v]+b2v);
  __syncthreads();
  for (int v=t; v<NN; v+=1024){
    int b = batch[v];
    float e = __expf(gate[v]+b2v - smax[b]);
    gate[v] = e;
    atomicAdd(&ssum[b], e);
  }
  __syncthreads();
  if (t < GG) gsum[t] = ssum[t];
}

__global__ __launch_bounds__(256)
void emb_kernel(const float* __restrict__ gate, const int* __restrict__ batch,
                const float* __restrict__ gsum, const float* __restrict__ h, float* __restrict__ emb){
  int w = (blockIdx.x*blockDim.x + threadIdx.x)>>5;
  int lane = threadIdx.x & 31;
  if (w >= NN) return;
  int b = batch[w];
  float c = gate[w]/(gsum[b]+1e-16f);
  #pragma unroll
  for (int k=0;k<8;k++) atomicAdd(&emb[b*HD + k*32 + lane], c*h[w*HD + k*32 + lane]);
}

// ---------------- label heads: grid (OO,2), 128 thr, hidden-split ----------------
__global__ __launch_bounds__(128)
void head_kernel(const float* __restrict__ emb, const float* __restrict__ W1,
                 const float* __restrict__ b1, const float* __restrict__ g,
                 const float* __restrict__ be, const float* __restrict__ W2,
                 float* __restrict__ out){
  __shared__ float embS[GG*HD];
  __shared__ float sred[GG];
  int o = blockIdx.x;
  int half = blockIdx.y;
  int t = threadIdx.x;
  int hu = half*128 + t;
  for (int i=t;i<GG*HD;i+=128) embS[i]=emb[i];
  if (t < GG) sred[t]=0.f;
  __syncthreads();
  float acc[GG];
  #pragma unroll
  for (int b=0;b<GG;b++) acc[b]=0.f;
  const float* w = W1 + (long)o*HD*256 + hu;
  for (int d=0;d<HD;d++){
    float wv = w[(long)d*256];
    #pragma unroll
    for (int b=0;b<GG;b++) acc[b] += embS[b*HD+d]*wv;
  }
  const float BNS = rsqrtf(1.0f + 1e-5f);
  float bnscale = g[o*256+hu]*BNS;
  float beta = be[o*256+hu];
  float bb1 = b1[o*256+hu];
  float w2 = W2[o*256+hu];
  #pragma unroll
  for (int b=0;b<GG;b++){
    float z = acc[b]+bb1;
    float sv = z/(1.f+__expf(-z));
    float bnv = sv*bnscale + beta;
    atomicAdd(&sred[b], bnv*w2);
  }
  __syncthreads();
  if (t < GG) atomicAdd(&out[t*OO + o], sred[t]);
}

// ---------------- host launch ----------------
extern "C" void kernel_launch(void* const* d_in, const int* in_sizes, int n_in,
                              void* d_out, int out_size) {
  (void)in_sizes; (void)n_in; (void)out_size;
  const float* x      = (const float*)d_in[0];
  const int*   ei     = (const int*)  d_in[1];
  const int*   batch  = (const int*)  d_in[2];
  const float* fp_W   = (const float*)d_in[3];
  const float* fp_b   = (const float*)d_in[4];
  const float* fp_g   = (const float*)d_in[5];
  const float* fp_be  = (const float*)d_in[6];
  const float* gat_Wl = (const float*)d_in[7];
  const float* gat_bl = (const float*)d_in[8];
  const float* gat_Wr = (const float*)d_in[9];
  const float* gat_br = (const float*)d_in[10];
  const float* gat_att= (const float*)d_in[11];
  const float* gat_bias=(const float*)d_in[12];
  const float* gin_W  = (const float*)d_in[13];
  const float* gin_b  = (const float*)d_in[14];
  const float* gin_g  = (const float*)d_in[15];
  const float* gin_be = (const float*)d_in[16];
  const float* ln_g   = (const float*)d_in[17];
  const float* ln_b   = (const float*)d_in[18];
  const float* res_W  = (const float*)d_in[19];
  const float* res_b  = (const float*)d_in[20];
  const float* pool_W1= (const float*)d_in[21];
  const float* pool_b1= (const float*)d_in[22];
  const float* pool_W2= (const float*)d_in[23];
  const float* pool_b2= (const float*)d_in[24];
  const float* head_W1= (const float*)d_in[25];
  const float* head_b1= (const float*)d_in[26];
  const float* head_g = (const float*)d_in[27];
  const float* head_be= (const float*)d_in[28];
  const float* head_W2= (const float*)d_in[29];
  const float* head_b2= (const float*)d_in[30];

  float *h0,*h1,*xl,*xr,*rw,*red,*gate,*gsum,*emb;
  int *degGat,*degGin,*ptrGat,*ptrGin,*curGat,*curGin,*colGat,*colGin;
  cudaGetSymbolAddress((void**)&h0, d_h0);
  cudaGetSymbolAddress((void**)&h1, d_h1);
  cudaGetSymbolAddress((void**)&xl, d_xl);
  cudaGetSymbolAddress((void**)&xr, d_xr);
  cudaGetSymbolAddress((void**)&rw, d_rw);
  cudaGetSymbolAddress((void**)&red, d_red);
  cudaGetSymbolAddress((void**)&gate, d_gate);
  cudaGetSymbolAddress((void**)&gsum, d_gsum);
  cudaGetSymbolAddress((void**)&emb, d_emb);
  cudaGetSymbolAddress((void**)&degGat, d_degGat);
  cudaGetSymbolAddress((void**)&degGin, d_degGin);
  cudaGetSymbolAddress((void**)&ptrGat, d_ptrGat);
  cudaGetSymbolAddress((void**)&ptrGin, d_ptrGin);
  cudaGetSymbolAddress((void**)&curGat, d_curGat);
  cudaGetSymbolAddress((void**)&curGin, d_curGin);
  cudaGetSymbolAddress((void**)&colGat, d_colGat);
  cudaGetSymbolAddress((void**)&colGin, d_colGin);

  cudaFuncSetAttribute(gemm_tc<EPI_RELU_BN,false>, cudaFuncAttributeMaxDynamicSharedMemorySize, SMEM_SZ);
  cudaFuncSetAttribute(gemm_tc<EPI_BIAS,true>,     cudaFuncAttributeMaxDynamicSharedMemorySize, SMEM_SZ);
  cudaFuncSetAttribute(gemm_tc<EPI_GIN,false>,     cudaFuncAttributeMaxDynamicSharedMemorySize, SMEM_SZ);
  cudaFuncSetAttribute(gemm_tc<EPI_RES,false>,     cudaFuncAttributeMaxDynamicSharedMemorySize, SMEM_SZ);
  cudaFuncSetAttribute(gemm_tc<EPI_POOL,false>,    cudaFuncAttributeMaxDynamicSharedMemorySize, SMEM_SZ);

  dim3 gg1(NN/128, 1);
  dim3 gg2(NN/128, 2);

  initro_kernel<<<896, 256>>>(degGat, degGin, red, emb, gate, (float*)d_out, head_b2,
                              fp_W, gat_Wl, gat_Wr, gin_W, res_W, pool_W1, rw);
  hist_kernel<<<(EP+255)/256, 256>>>(ei, degGat, degGin);
  scan2_kernel<<<2, 1024>>>(degGat, ptrGat, curGat, degGin, ptrGin, curGin);
  // feature projection: h0 = bn(relu(x @ fp_W + fp_b))   <-- ncu capture target (#4)
  gemm_tc<EPI_RELU_BN,false><<<gg1,256,SMEM_SZ>>>(x, rw+FPW_OFF, fp_b, nullptr,nullptr,nullptr,
      fp_g, fp_be, nullptr,nullptr,nullptr,nullptr,nullptr,nullptr,nullptr, h0, DIN);
  fill_kernel<<<(EP+255)/256, 256>>>(ei, curGat, colGat, curGin, colGin);

  float* cur = h0;
  float* alt = h1;
  for (int i=0;i<2;i++){
    const float* Wl = rw + WL_OFF + (long)i*HD*HD;
    const float* bl = gat_bl + (long)i*HD;
    const float* Wr = rw + WR_OFF + (long)i*HD*HD;
    const float* br = gat_br + (long)i*HD;
    const float* at = gat_att + (long)i*8*32;
    const float* gb = gat_bias + (long)i*HD;
    const float* gW = rw + GINW_OFF + (long)i*HD*HD;
    const float* gbi= gin_b + (long)i*HD;
    const float* ggm= gin_g + (long)i*HD;
    const float* gbe= gin_be + (long)i*HD;
    const float* lg = ln_g + (long)i*HD;
    const float* lb = ln_b + (long)i*HD;
    const float* rW = rw + RESW_OFF + (long)i*HD*HD;
    const float* rb = res_b + (long)i*HD;

    gemm_tc<EPI_BIAS,true><<<gg2,256,SMEM_SZ>>>(cur, Wl, bl, Wr, br, xr,
        nullptr,nullptr,nullptr,nullptr,nullptr,nullptr,nullptr,nullptr,nullptr, xl, HD);
    gat_kernel<<<NN/8, 256>>>((const float4*)xl, (const float4*)xr, ptrGat, colGat, at, gb, alt);
    { float* t = cur; cur = alt; alt = t; }

    ginagg_kernel<<<NN/8, 256>>>((const float4*)cur, ptrGin, colGin, xl);
    gemm_tc<EPI_GIN,false><<<gg1,256,SMEM_SZ>>>(xl, gW, gbi, nullptr,nullptr,nullptr,
        ggm, gbe, nullptr,nullptr,nullptr,nullptr, red + 2*i, nullptr,nullptr, alt, HD);
    { float* t = cur; cur = alt; alt = t; }

    gemm_tc<EPI_RES,false><<<gg1,256,SMEM_SZ>>>(cur, rW, rb, nullptr,nullptr,nullptr,
        nullptr,nullptr, lg, lb, cur, red + 2*i, nullptr,nullptr,nullptr, alt, HD);
    { float* t = cur; cur = alt; alt = t; }
  }

  gemm_tc<EPI_POOL,false><<<gg1,256,SMEM_SZ>>>(cur, rw+POOLW_OFF, pool_b1, nullptr,nullptr,nullptr,
      nullptr,nullptr,nullptr,nullptr,nullptr,nullptr,nullptr, pool_W2, gate, nullptr, HD);
  bsoftmax_kernel<<<1, 1024>>>(gate, batch, pool_b2, gsum);
  emb_kernel<<<NN/8, 256>>>(gate, batch, gsum, cur, emb);

  head_kernel<<<dim3(OO,2), 128>>>(emb, head_W1, head_b1, head_g, head_be, head_W2, (float*)d_out);
}

// round 12
// speedup vs baseline: 1.0164x; 1.0164x over previous
#include <cuda_runtime.h>
#include <stdint.h>
#include <math.h>

#define NN 16000
#define EE 256000
#define EP (EE+NN)
#define DIN 1280
#define HD 256
#define GG 32
#define OO 64

// rounded-weight scratch layout (floats)
#define FPW_OFF   0
#define WL_OFF    327680
#define WR_OFF    458752
#define GINW_OFF  589824
#define RESW_OFF  720896
#define POOLW_OFF 851968
#define RW_TOT    917504

// dynamic smem for gemm: As[3][128][20] + Bs[3][16][264]
#define AS_STRIDE 2560
#define BS_STRIDE 4224
#define AS_FLOATS (3*AS_STRIDE)
#define BS_FLOATS (3*BS_STRIDE)
#define SMEM_SZ ((AS_FLOATS + BS_FLOATS)*4)

// ---------------- device scratch (static, allocation-free) ----------------
__device__ float d_h0[NN*HD];
__device__ float d_h1[NN*HD];
__device__ float d_xl[NN*HD];
__device__ float d_xr[NN*HD];
__device__ float d_rw[RW_TOT];
__device__ int   d_degGat[NN];
__device__ int   d_ptrGat[NN+1];
__device__ int   d_curGat[NN];
__device__ int   d_colGat[EP];
__device__ float d_red[4];
__device__ float d_gate[NN], d_gsum[GG], d_emb[GG*HD];

__device__ __forceinline__ void atomicMaxF(float* addr, float v){
  if (v >= 0.f) atomicMax((int*)addr, __float_as_int(v));
  else          atomicMin((unsigned int*)addr, __float_as_uint(v));
}

__device__ __forceinline__ uint32_t tf32u(float x){
  uint32_t u; asm("cvt.rna.tf32.f32 %0, %1;" : "=r"(u) : "f"(x));
  return u;
}

#define CP16(dst, src) asm volatile("cp.async.cg.shared.global [%0], [%1], 16;\n" :: "r"(dst), "l"(src))
#define CP_COMMIT()    asm volatile("cp.async.commit_group;\n" ::)
template<int N>
__device__ __forceinline__ void cp_wait(){ asm volatile("cp.async.wait_group %0;\n" :: "n"(N)); }

// ---------------- init + weight pre-round (fused) ----------------
__global__ void initro_kernel(int* degGat,float* red,float* emb,float* gate,
                              float* out, const float* __restrict__ head_b2,
                              const float* __restrict__ fpW, const float* __restrict__ wl,
                              const float* __restrict__ wr, const float* __restrict__ ginw,
                              const float* __restrict__ resw, const float* __restrict__ poolw,
                              float* __restrict__ rw){
  int i = blockIdx.x*blockDim.x+threadIdx.x;
  if (i < NN){ degGat[i]=0; gate[i]=0.f; }
  if (i < 4)  red[i]=0.f;
  if (i < GG*HD) emb[i]=0.f;
  if (i < GG*OO) out[i] = head_b2[i % OO];
  for (int idx = i; idx < RW_TOT; idx += gridDim.x*blockDim.x){
    float v; int j = idx;
    if (j < 327680) v = fpW[j];
    else { j -= 327680;
      if (j < 131072) v = wl[j];
      else { j -= 131072;
        if (j < 131072) v = wr[j];
        else { j -= 131072;
          if (j < 131072) v = ginw[j];
          else { j -= 131072;
            if (j < 131072) v = resw[j];
            else v = poolw[j-131072];
          }
        }
      }
    }
    rw[idx] = __uint_as_float(tf32u(v));
  }
}

__global__ void hist_kernel(const int* __restrict__ ei, int* degGat){
  int e = blockIdx.x*blockDim.x+threadIdx.x;
  if (e >= EP) return;
  int d = (e < EE) ? ei[EE+e] : (e-EE);
  atomicAdd(&degGat[d],1);
}

// shuffle-based scan: 1 block, 1024 threads, 16 elems/thread
__global__ void scan_kernel(const int* __restrict__ deg, int* indptr, int* cursor){
  int t = threadIdx.x;
  int lane = t & 31, wid = t >> 5;
  const int CH = 16;
  int st = t*CH;
  int dv[CH];
  int mySum = 0;
  #pragma unroll
  for (int i=0;i<CH;i++){
    int idx = st+i;
    dv[i] = (idx<NN)? deg[idx] : 0;
    mySum += dv[i];
  }
  int inc = mySum;
  #pragma unroll
  for (int off=1; off<32; off<<=1){
    int n = __shfl_up_sync(0xffffffffu, inc, off);
    if (lane >= off) inc += n;
  }
  __shared__ int wtot[32];
  if (lane==31) wtot[wid] = inc;
  __syncthreads();
  if (wid==0){
    int v = wtot[lane];
    #pragma unroll
    for (int off=1; off<32; off<<=1){
      int n = __shfl_up_sync(0xffffffffu, v, off);
      if (lane >= off) v += n;
    }
    wtot[lane] = v;
  }
  __syncthreads();
  int run = inc - mySum + (wid>0 ? wtot[wid-1] : 0);
  #pragma unroll
  for (int i=0;i<CH;i++){
    int idx = st+i;
    if (idx<NN){ indptr[idx]=run; cursor[idx]=run; run+=dv[i]; }
  }
  if (t==1023) indptr[NN] = wtot[31];
}

__global__ void fill_kernel(const int* __restrict__ ei, int* curGat, int* colGat){
  int e = blockIdx.x*blockDim.x+threadIdx.x;
  if (e >= EP) return;
  if (e < EE){
    colGat[atomicAdd(&curGat[ei[EE+e]],1)] = ei[e];
  } else {
    int v = e-EE;
    colGat[atomicAdd(&curGat[v],1)] = v;
  }
}

// --- 128x256-tile tf32 GEMM, 8 warps of 64x64, 3-stage cp.async, fused epi ---
enum { EPI_BIAS=0, EPI_RELU_BN=1, EPI_GIN=2, EPI_RES=3, EPI_POOL=4 };

template<int EPI, bool DUAL>
__global__ __launch_bounds__(256)
void gemm_tc(const float* __restrict__ A,
             const float* __restrict__ B,  const float* __restrict__ bias,
             const float* __restrict__ B2, const float* __restrict__ bias2, float* __restrict__ C2,
             const float* __restrict__ g,   const float* __restrict__ be,
             const float* __restrict__ lng, const float* __restrict__ lnb,
             const float* __restrict__ hres,
             const float* __restrict__ stats, float* __restrict__ statsOut,
             const float* __restrict__ W2pool, float* __restrict__ gatebuf,
             float* __restrict__ C, int K)
{
  extern __shared__ float sm[];
  float* AsP = sm;
  float* BsP = sm + AS_FLOATS;
  int tid = threadIdx.x;
  int lane = tid & 31, w = tid >> 5;
  int warpM = (w >> 2) * 64;
  int warpN = (w & 3) * 64;
  int m0 = blockIdx.x * 128;
  const float* Bp = B; const float* biasp = bias; float* Cp = C;
  if (DUAL && blockIdx.y == 1){ Bp = B2; biasp = bias2; Cp = C2; }
  int tg = lane >> 2, tk = lane & 3;

  float acc[4][8][4];
  #pragma unroll
  for (int i=0;i<4;i++)
    #pragma unroll
    for (int j=0;j<8;j++)
      #pragma unroll
      for (int r=0;r<4;r++) acc[i][j][r]=0.f;

  int rowA  = tid >> 2;
  int k4A   = (tid & 3) * 4;
  int krB = tid >> 4;
  int nbB = (tid & 15)*4;

  uint32_t sA0[3], sA1[3], sB[3];
  #pragma unroll
  for (int s=0;s<3;s++){
    sA0[s] = (uint32_t)__cvta_generic_to_shared(&AsP[s*AS_STRIDE + rowA*20 + k4A]);
    sA1[s] = (uint32_t)__cvta_generic_to_shared(&AsP[s*AS_STRIDE + (rowA+64)*20 + k4A]);
    sB[s]  = (uint32_t)__cvta_generic_to_shared(&BsP[s*BS_STRIDE + krB*264 + nbB]);
  }
  const float* gA0 = A  + (long)(m0+rowA   )*K + k4A;
  const float* gA1 = A  + (long)(m0+rowA+64)*K + k4A;
  const float* gB  = Bp + (long)krB*HD + nbB;

  int nk = K >> 4;
  // prologue: stages 0 and 1
  CP16(sA0[0], gA0); CP16(sA1[0], gA1);
  #pragma unroll
  for (int c4=0;c4<4;c4++) CP16(sB[0] + c4*256, gB + c4*64);
  CP_COMMIT();
  if (nk > 1){
    CP16(sA0[1], gA0+16); CP16(sA1[1], gA1+16);
    const float* gBk = gB + (long)16*HD;
    #pragma unroll
    for (int c4=0;c4<4;c4++) CP16(sB[1] + c4*256, gBk + c4*64);
    CP_COMMIT();
  }

  int st = 0;
  for (int kt=0; kt<nk; kt++){
    if (kt+1 < nk) cp_wait<1>(); else cp_wait<0>();
    __syncthreads();
    if (kt+2 < nk){
      int s2 = st+2; if (s2>=3) s2-=3;
      int kb = (kt+2)<<4;
      CP16(sA0[s2], gA0+kb); CP16(sA1[s2], gA1+kb);
      const float* gBk = gB + (long)kb*HD;
      #pragma unroll
      for (int c4=0;c4<4;c4++) CP16(sB[s2] + c4*256, gBk + c4*64);
      CP_COMMIT();
    }
    const float* Abase = AsP + st*AS_STRIDE;
    const float* Bbase = BsP + st*BS_STRIDE;
    #pragma unroll
    for (int ks=0; ks<2; ks++){
      int k0 = ks*8;
      uint32_t a[4][4], b[8][2];
      #pragma unroll
      for (int i=0;i<4;i++){
        int r = warpM + i*16 + tg;
        a[i][0] = tf32u(Abase[(r  )*20 + k0+tk  ]);
        a[i][1] = tf32u(Abase[(r+8)*20 + k0+tk  ]);
        a[i][2] = tf32u(Abase[(r  )*20 + k0+tk+4]);
        a[i][3] = tf32u(Abase[(r+8)*20 + k0+tk+4]);
      }
      #pragma unroll
      for (int j=0;j<8;j++){
        int c = warpN + j*8 + tg;
        b[j][0] = __float_as_uint(Bbase[(k0+tk  )*264 + c]);
        b[j][1] = __float_as_uint(Bbase[(k0+tk+4)*264 + c]);
      }
      #pragma unroll
      for (int i=0;i<4;i++)
        #pragma unroll
        for (int j=0;j<8;j++)
          asm volatile("mma.sync.aligned.m16n8k8.row.col.f32.tf32.tf32.f32 "
            "{%0,%1,%2,%3}, {%4,%5,%6,%7}, {%8,%9}, {%0,%1,%2,%3};"
            : "+f"(acc[i][j][0]), "+f"(acc[i][j][1]),
              "+f"(acc[i][j][2]), "+f"(acc[i][j][3])
            : "r"(a[i][0]), "r"(a[i][1]), "r"(a[i][2]), "r"(a[i][3]),
              "r"(b[j][0]), "r"(b[j][1]));
    }
    st++; if (st>=3) st-=3;
  }

  // ---- epilogue ----
  const float BNS = rsqrtf(1.0f + 1e-5f);
  float mean=0.f, rdenom=1.f;
  if (EPI==EPI_RES){
    const float inv = 1.0f/((float)NN*(float)HD);
    mean = stats[0]*inv;
    float var = stats[1]*inv - mean*mean;
    rdenom = 1.f/(sqrtf(fmaxf(var,0.f)) + 1e-5f);
  }
  float ssum=0.f, sq=0.f;
  float pgate[4][2];
  if (EPI==EPI_POOL){
    #pragma unroll
    for (int i=0;i<4;i++){ pgate[i][0]=0.f; pgate[i][1]=0.f; }
  }
  #pragma unroll
  for (int j=0;j<8;j++){
    int col = warpN + j*8 + tk*2;
    float b0 = biasp[col], b1 = biasp[col+1];
    float g0=0.f,g1=0.f,e0=0.f,e1=0.f;
    if (EPI==EPI_RELU_BN || EPI==EPI_GIN){
      g0=g[col]*BNS; g1=g[col+1]*BNS; e0=be[col]; e1=be[col+1];
    }
    float lg0=0.f,lg1=0.f,lb0=0.f,lb1=0.f;
    if (EPI==EPI_RES){
      lg0=lng[col]; lg1=lng[col+1]; lb0=lnb[col]; lb1=lnb[col+1];
    }
    float w20=0.f,w21=0.f;
    if (EPI==EPI_POOL){ w20=W2pool[col]; w21=W2pool[col+1]; }
    #pragma unroll
    for (int i=0;i<4;i++){
      #pragma unroll
      for (int h=0;h<2;h++){
        int row = m0 + warpM + i*16 + tg + h*8;
        float v0 = acc[i][j][h*2+0] + b0;
        float v1 = acc[i][j][h*2+1] + b1;
        if (EPI==EPI_RELU_BN){
          v0 = fmaxf(v0,0.f)*g0 + e0;
          v1 = fmaxf(v1,0.f)*g1 + e1;
        } else if (EPI==EPI_GIN){
          v0 = fmaxf(v0,0.f)*g0 + e0; v0 = (v0>0.f)? v0 : 0.2f*v0;
          v1 = fmaxf(v1,0.f)*g1 + e1; v1 = (v1>0.f)? v1 : 0.2f*v1;
          ssum += v0+v1; sq += v0*v0+v1*v1;
        } else if (EPI==EPI_RES){
          float2 hv = *(const float2*)&hres[(long)row*HD + col];
          v0 += (hv.x-mean)*rdenom*lg0 + lb0;
          v1 += (hv.y-mean)*rdenom*lg1 + lb1;
          v0 = (v0>0.f)? v0 : 0.2f*v0;
          v1 = (v1>0.f)? v1 : 0.2f*v1;
        } else if (EPI==EPI_POOL){
          pgate[i][h] += tanhf(v0)*w20 + tanhf(v1)*w21;
        }
        if (EPI!=EPI_POOL)
          *(float2*)&Cp[(long)row*HD + col] = make_float2(v0,v1);
      }
    }
  }
  if (EPI==EPI_GIN){
    #pragma unroll
    for (int off=16; off>0; off>>=1){
      ssum += __shfl_xor_sync(0xffffffffu, ssum, off);
      sq   += __shfl_xor_sync(0xffffffffu, sq,   off);
    }
    if (lane==0){
      atomicAdd(&statsOut[0], ssum);
      atomicAdd(&statsOut[1], sq);
    }
  }
  if (EPI==EPI_POOL){
    #pragma unroll
    for (int i=0;i<4;i++)
      #pragma unroll
      for (int h=0;h<2;h++){
        float p = pgate[i][h];
        p += __shfl_xor_sync(0xffffffffu, p, 1);
        p += __shfl_xor_sync(0xffffffffu, p, 2);
        if (tk==0){
          int row = m0 + warpM + i*16 + tg + h*8;
          atomicAdd(&gatebuf[row], p);
        }
      }
  }
}

// ------- GATv2: 2 warps per node (half edge-lists), float4 lanes -------
__device__ __forceinline__ void gat_edge_logits(
    const float4& x0, const float4& x1,
    const float4& xr0, const float4& xr1,
    const float4& a0, const float4& a1,
    float& q0, float& q1)
{
  float v;
  v = x0.x+xr0.x; v = v>0.f?v:0.2f*v; q0  = v*a0.x;
  v = x0.y+xr0.y; v = v>0.f?v:0.2f*v; q0 += v*a0.y;
  v = x0.z+xr0.z; v = v>0.f?v:0.2f*v; q0 += v*a0.z;
  v = x0.w+xr0.w; v = v>0.f?v:0.2f*v; q0 += v*a0.w;
  v = x1.x+xr1.x; v = v>0.f?v:0.2f*v; q1  = v*a1.x;
  v = x1.y+xr1.y; v = v>0.f?v:0.2f*v; q1 += v*a1.y;
  v = x1.z+xr1.z; v = v>0.f?v:0.2f*v; q1 += v*a1.z;
  v = x1.w+xr1.w; v = v>0.f?v:0.2f*v; q1 += v*a1.w;
}

__global__ __launch_bounds__(256)
void gat_kernel(const float4* __restrict__ xl4, const float4* __restrict__ xr4,
                const int* __restrict__ indptr, const int* __restrict__ col,
                const float* __restrict__ att, const float* __restrict__ gbias,
                float* __restrict__ hout){
  __shared__ float part[4][32][10];
  int warpid = threadIdx.x >> 5;
  int lane = threadIdx.x & 31;
  int nib = warpid >> 1;
  int half = warpid & 1;
  int w = blockIdx.x*4 + nib;          // grid = NN/4, exact
  const float4* at4 = (const float4*)att;
  float4 a0 = at4[lane], a1 = at4[32+lane];
  float4 xr0 = xr4[w*64 + lane], xr1 = xr4[w*64 + 32 + lane];
  float4 acc0 = make_float4(0,0,0,0), acc1 = make_float4(0,0,0,0);
  float s0=0.f, s1=0.f;
  int p0 = indptr[w], p1 = indptr[w+1];
  int mid = p0 + ((p1-p0)+1)/2;
  int jb = half ? mid : p0;
  int je = half ? p1  : mid;
  int j = jb;
  for (; j+1 < je; j += 2){
    int ua = col[j], ub = col[j+1];
    float4 x0a = xl4[ua*64 + lane];
    float4 x1a = xl4[ua*64 + 32 + lane];
    float4 x0b = xl4[ub*64 + lane];
    float4 x1b = xl4[ub*64 + 32 + lane];
    float q0a,q1a,q0b,q1b;
    gat_edge_logits(x0a,x1a,xr0,xr1,a0,a1,q0a,q1a);
    gat_edge_logits(x0b,x1b,xr0,xr1,a0,a1,q0b,q1b);
    q0a += __shfl_xor_sync(0xffffffffu,q0a,1);
    q1a += __shfl_xor_sync(0xffffffffu,q1a,1);
    q0b += __shfl_xor_sync(0xffffffffu,q0b,1);
    q1b += __shfl_xor_sync(0xffffffffu,q1b,1);
    q0a += __shfl_xor_sync(0xffffffffu,q0a,2);
    q1a += __shfl_xor_sync(0xffffffffu,q1a,2);
    q0b += __shfl_xor_sync(0xffffffffu,q0b,2);
    q1b += __shfl_xor_sync(0xffffffffu,q1b,2);
    q0a += __shfl_xor_sync(0xffffffffu,q0a,4);
    q1a += __shfl_xor_sync(0xffffffffu,q1a,4);
    q0b += __shfl_xor_sync(0xffffffffu,q0b,4);
    q1b += __shfl_xor_sync(0xffffffffu,q1b,4);
    float c0a = __expf(q0a), c1a = __expf(q1a);
    float c0b = __expf(q0b), c1b = __expf(q1b);
    s0 += c0a; s1 += c1a;
    acc0.x += c0a*x0a.x; acc0.y += c0a*x0a.y; acc0.z += c0a*x0a.z; acc0.w += c0a*x0a.w;
    acc1.x += c1a*x1a.x; acc1.y += c1a*x1a.y; acc1.z += c1a*x1a.z; acc1.w += c1a*x1a.w;
    s0 += c0b; s1 += c1b;
    acc0.x += c0b*x0b.x; acc0.y += c0b*x0b.y; acc0.z += c0b*x0b.z; acc0.w += c0b*x0b.w;
    acc1.x += c1b*x1b.x; acc1.y += c1b*x1b.y; acc1.z += c1b*x1b.z; acc1.w += c1b*x1b.w;
  }
  if (j < je){
    int u = col[j];
    float4 x0 = xl4[u*64 + lane];
    float4 x1 = xl4[u*64 + 32 + lane];
    float q0,q1;
    gat_edge_logits(x0,x1,xr0,xr1,a0,a1,q0,q1);
    q0 += __shfl_xor_sync(0xffffffffu,q0,1);
    q1 += __shfl_xor_sync(0xffffffffu,q1,1);
    q0 += __shfl_xor_sync(0xffffffffu,q0,2);
    q1 += __shfl_xor_sync(0xffffffffu,q1,2);
    q0 += __shfl_xor_sync(0xffffffffu,q0,4);
    q1 += __shfl_xor_sync(0xffffffffu,q1,4);
    float c0 = __expf(q0), c1 = __expf(q1);
    s0 += c0; s1 += c1;
    acc0.x += c0*x0.x; acc0.y += c0*x0.y; acc0.z += c0*x0.z; acc0.w += c0*x0.w;
    acc1.x += c1*x1.x; acc1.y += c1*x1.y; acc1.z += c1*x1.z; acc1.w += c1*x1.w;
  }
  if (half == 1){
    part[nib][lane][0] = acc0.x; part[nib][lane][1] = acc0.y;
    part[nib][lane][2] = acc0.z; part[nib][lane][3] = acc0.w;
    part[nib][lane][4] = acc1.x; part[nib][lane][5] = acc1.y;
    part[nib][lane][6] = acc1.z; part[nib][lane][7] = acc1.w;
    part[nib][lane][8] = s0;     part[nib][lane][9] = s1;
  }
  __syncthreads();
  if (half == 0){
    acc0.x += part[nib][lane][0]; acc0.y += part[nib][lane][1];
    acc0.z += part[nib][lane][2]; acc0.w += part[nib][lane][3];
    acc1.x += part[nib][lane][4]; acc1.y += part[nib][lane][5];
    acc1.z += part[nib][lane][6]; acc1.w += part[nib][lane][7];
    s0 += part[nib][lane][8];     s1 += part[nib][lane][9];
    float r0 = 1.f/(s0+1e-16f), r1 = 1.f/(s1+1e-16f);
    const float4* gb4 = (const float4*)gbias;
    float4 b0 = gb4[lane], b1 = gb4[32+lane];
    float4 o0, o1;
    o0.x=acc0.x*r0+b0.x; o0.y=acc0.y*r0+b0.y; o0.z=acc0.z*r0+b0.z; o0.w=acc0.w*r0+b0.w;
    o1.x=acc1.x*r1+b1.x; o1.y=acc1.y*r1+b1.y; o1.z=acc1.z*r1+b1.z; o1.w=acc1.w*r1+b1.w;
    ((float4*)hout)[w*64 + lane]      = o0;
    ((float4*)hout)[w*64 + 32 + lane] = o1;
  }
}

// ---- GIN aggregation via GAT CSR (self-loop already in list), 2 warps/node ----
__global__ __launch_bounds__(256)
void ginagg_kernel(const float4* __restrict__ h4, const int* __restrict__ indptr,
                   const int* __restrict__ col, float* __restrict__ tmp){
  __shared__ float part[4][32][8];
  int warpid = threadIdx.x >> 5;
  int lane = threadIdx.x & 31;
  int nib = warpid >> 1;
  int half = warpid & 1;
  int w = blockIdx.x*4 + nib;
  float4 acc0 = make_float4(0,0,0,0), acc1 = make_float4(0,0,0,0);
  int p0 = indptr[w], p1 = indptr[w+1];
  int mid = p0 + ((p1-p0)+1)/2;
  int jb = half ? mid : p0;
  int je = half ? p1  : mid;
  int j = jb;
  for (; j+3 < je; j += 4){
    int u0 = col[j], u1 = col[j+1], u2 = col[j+2], u3 = col[j+3];
    float4 x00 = h4[u0*64 + lane], x01 = h4[u0*64 + 32 + lane];
    float4 x10 = h4[u1*64 + lane], x11 = h4[u1*64 + 32 + lane];
    float4 x20 = h4[u2*64 + lane], x21 = h4[u2*64 + 32 + lane];
    float4 x30 = h4[u3*64 + lane], x31 = h4[u3*64 + 32 + lane];
    acc0.x+=x00.x; acc0.y+=x00.y; acc0.z+=x00.z; acc0.w+=x00.w;
    acc1.x+=x01.x; acc1.y+=x01.y; acc1.z+=x01.z; acc1.w+=x01.w;
    acc0.x+=x10.x; acc0.y+=x10.y; acc0.z+=x10.z; acc0.w+=x10.w;
    acc1.x+=x11.x; acc1.y+=x11.y; acc1.z+=x11.z; acc1.w+=x11.w;
    acc0.x+=x20.x; acc0.y+=x20.y; acc0.z+=x20.z; acc0.w+=x20.w;
    acc1.x+=x21.x; acc1.y+=x21.y; acc1.z+=x21.z; acc1.w+=x21.w;
    acc0.x+=x30.x; acc0.y+=x30.y; acc0.z+=x30.z; acc0.w+=x30.w;
    acc1.x+=x31.x; acc1.y+=x31.y; acc1.z+=x31.z; acc1.w+=x31.w;
  }
  for (; j < je; j++){
    int u = col[j];
    float4 x0 = h4[u*64 + lane];
    float4 x1 = h4[u*64 + 32 + lane];
    acc0.x+=x0.x; acc0.y+=x0.y; acc0.z+=x0.z; acc0.w+=x0.w;
    acc1.x+=x1.x; acc1.y+=x1.y; acc1.z+=x1.z; acc1.w+=x1.w;
  }
  if (half == 1){
    part[nib][lane][0]=acc0.x; part[nib][lane][1]=acc0.y;
    part[nib][lane][2]=acc0.z; part[nib][lane][3]=acc0.w;
    part[nib][lane][4]=acc1.x; part[nib][lane][5]=acc1.y;
    part[nib][lane][6]=acc1.z; part[nib][lane][7]=acc1.w;
  }
  __syncthreads();
  if (half == 0){
    acc0.x+=part[nib][lane][0]; acc0.y+=part[nib][lane][1];
    acc0.z+=part[nib][lane][2]; acc0.w+=part[nib][lane][3];
    acc1.x+=part[nib][lane][4]; acc1.y+=part[nib][lane][5];
    acc1.z+=part[nib][lane][6]; acc1.w+=part[nib][lane][7];
    ((float4*)tmp)[w*64 + lane]      = acc0;
    ((float4*)tmp)[w*64 + 32 + lane] = acc1;
  }
}

// ---------------- pooling: batch softmax (single block) ----------------
__global__ void bsoftmax_kernel(float* __restrict__ gate, const int* __restrict__ batch,
                                const float* __restrict__ b2, float* __restrict__ gsum){
  __shared__ float smax[GG], ssum[GG];
  int t = threadIdx.x;  // 1024 threads
  if (t < GG){ smax[t] = -1e30f; ssum[t] = 0.f; }
  __syncthreads();
  float b2v = b2[0];
  for (int v=t; v<NN; v+=1024)
    atomicMaxF(&smax[batch[v]], gate[v]+b2v);
  __syncthreads();
  for (int v=t; v<NN; v+=1024){
    int b = batch[v];
    float e = __expf(gate[v]+b2v - smax[b]);
    gate[v] = e;
    atomicAdd(&ssum[b], e);
  }
  __syncthreads();
  if (t < GG) gsum[t] = ssum[t];
}

__global__ __launch_bounds__(256)
void emb_kernel(const float* __restrict__ gate, const int* __restrict__ batch,
                const float* __restrict__ gsum, const float* __restrict__ h, float* __restrict__ emb){
  int w = (blockIdx.x*blockDim.x + threadIdx.x)>>5;
  int lane = threadIdx.x & 31;
  if (w >= NN) return;
  int b = batch[w];
  float c = gate[w]/(gsum[b]+1e-16f);
  #pragma unroll
  for (int k=0;k<8;k++) atomicAdd(&emb[b*HD + k*32 + lane], c*h[w*HD + k*32 + lane]);
}

// ---------------- label heads: grid (OO,2), 128 thr, hidden-split ----------------
__global__ __launch_bounds__(128)
void head_kernel(const float* __restrict__ emb, const float* __restrict__ W1,
                 const float* __restrict__ b1, const float* __restrict__ g,
                 const float* __restrict__ be, const float* __restrict__ W2,
                 float* __restrict__ out){
  __shared__ float embS[GG*HD];
  __shared__ float sred[GG];
  int o = blockIdx.x;
  int half = blockIdx.y;
  int t = threadIdx.x;
  int hu = half*128 + t;
  for (int i=t;i<GG*HD;i+=128) embS[i]=emb[i];
  if (t < GG) sred[t]=0.f;
  __syncthreads();
  float acc[GG];
  #pragma unroll
  for (int b=0;b<GG;b++) acc[b]=0.f;
  const float* w = W1 + (long)o*HD*256 + hu;
  for (int d=0;d<HD;d++){
    float wv = w[(long)d*256];
    #pragma unroll
    for (int b=0;b<GG;b++) acc[b] += embS[b*HD+d]*wv;
  }
  const float BNS = rsqrtf(1.0f + 1e-5f);
  float bnscale = g[o*256+hu]*BNS;
  float beta = be[o*256+hu];
  float bb1 = b1[o*256+hu];
  float w2 = W2[o*256+hu];
  #pragma unroll
  for (int b=0;b<GG;b++){
    float z = acc[b]+bb1;
    float sv = z/(1.f+__expf(-z));
    float bnv = sv*bnscale + beta;
    atomicAdd(&sred[b], bnv*w2);
  }
  __syncthreads();
  if (t < GG) atomicAdd(&out[t*OO + o], sred[t]);
}

// ---------------- host launch ----------------
extern "C" void kernel_launch(void* const* d_in, const int* in_sizes, int n_in,
                              void* d_out, int out_size) {
  (void)in_sizes; (void)n_in; (void)out_size;
  const float* x      = (const float*)d_in[0];
  const int*   ei     = (const int*)  d_in[1];
  const int*   batch  = (const int*)  d_in[2];
  const float* fp_W   = (const float*)d_in[3];
  const float* fp_b   = (const float*)d_in[4];
  const float* fp_g   = (const float*)d_in[5];
  const float* fp_be  = (const float*)d_in[6];
  const float* gat_Wl = (const float*)d_in[7];
  const float* gat_bl = (const float*)d_in[8];
  const float* gat_Wr = (const float*)d_in[9];
  const float* gat_br = (const float*)d_in[10];
  const float* gat_att= (const float*)d_in[11];
  const float* gat_bias=(const float*)d_in[12];
  const float* gin_W  = (const float*)d_in[13];
  const float* gin_b  = (const float*)d_in[14];
  const float* gin_g  = (const float*)d_in[15];
  const float* gin_be = (const float*)d_in[16];
  const float* ln_g   = (const float*)d_in[17];
  const float* ln_b   = (const float*)d_in[18];
  const float* res_W  = (const float*)d_in[19];
  const float* res_b  = (const float*)d_in[20];
  const float* pool_W1= (const float*)d_in[21];
  const float* pool_b1= (const float*)d_in[22];
  const float* pool_W2= (const float*)d_in[23];
  const float* pool_b2= (const float*)d_in[24];
  const float* head_W1= (const float*)d_in[25];
  const float* head_b1= (const float*)d_in[26];
  const float* head_g = (const float*)d_in[27];
  const float* head_be= (const float*)d_in[28];
  const float* head_W2= (const float*)d_in[29];
  const float* head_b2= (const float*)d_in[30];

  float *h0,*h1,*xl,*xr,*rw,*red,*gate,*gsum,*emb;
  int *degGat,*ptrGat,*curGat,*colGat;
  cudaGetSymbolAddress((void**)&h0, d_h0);
  cudaGetSymbolAddress((void**)&h1, d_h1);
  cudaGetSymbolAddress((void**)&xl, d_xl);
  cudaGetSymbolAddress((void**)&xr, d_xr);
  cudaGetSymbolAddress((void**)&rw, d_rw);
  cudaGetSymbolAddress((void**)&red, d_red);
  cudaGetSymbolAddress((void**)&gate, d_gate);
  cudaGetSymbolAddress((void**)&gsum, d_gsum);
  cudaGetSymbolAddress((void**)&emb, d_emb);
  cudaGetSymbolAddress((void**)&degGat, d_degGat);
  cudaGetSymbolAddress((void**)&ptrGat, d_ptrGat);
  cudaGetSymbolAddress((void**)&curGat, d_curGat);
  cudaGetSymbolAddress((void**)&colGat, d_colGat);

  cudaFuncSetAttribute(gemm_tc<EPI_RELU_BN,false>, cudaFuncAttributeMaxDynamicSharedMemorySize, SMEM_SZ);
  cudaFuncSetAttribute(gemm_tc<EPI_BIAS,true>,     cudaFuncAttributeMaxDynamicSharedMemorySize, SMEM_SZ);
  cudaFuncSetAttribute(gemm_tc<EPI_GIN,false>,     cudaFuncAttributeMaxDynamicSharedMemorySize, SMEM_SZ);
  cudaFuncSetAttribute(gemm_tc<EPI_RES,false>,     cudaFuncAttributeMaxDynamicSharedMemorySize, SMEM_SZ);
  cudaFuncSetAttribute(gemm_tc<EPI_POOL,false>,    cudaFuncAttributeMaxDynamicSharedMemorySize, SMEM_SZ);

  dim3 gg1(NN/128, 1);
  dim3 gg2(NN/128, 2);

  initro_kernel<<<896, 256>>>(degGat, red, emb, gate, (float*)d_out, head_b2,
                              fp_W, gat_Wl, gat_Wr, gin_W, res_W, pool_W1, rw);
  hist_kernel<<<(EP+255)/256, 256>>>(ei, degGat);
  scan_kernel<<<1, 1024>>>(degGat, ptrGat, curGat);
  // feature projection: h0 = bn(relu(x @ fp_W + fp_b))   <-- ncu capture target (#4)
  gemm_tc<EPI_RELU_BN,false><<<gg1,256,SMEM_SZ>>>(x, rw+FPW_OFF, fp_b, nullptr,nullptr,nullptr,
      fp_g, fp_be, nullptr,nullptr,nullptr,nullptr,nullptr,nullptr,nullptr, h0, DIN);
  fill_kernel<<<(EP+255)/256, 256>>>(ei, curGat, colGat);

  float* cur = h0;
  float* alt = h1;
  for (int i=0;i<2;i++){
    const float* Wl = rw + WL_OFF + (long)i*HD*HD;
    const float* bl = gat_bl + (long)i*HD;
    const float* Wr = rw + WR_OFF + (long)i*HD*HD;
    const float* br = gat_br + (long)i*HD;
    const float* at = gat_att + (long)i*8*32;
    const float* gb = gat_bias + (long)i*HD;
    const float* gW = rw + GINW_OFF + (long)i*HD*HD;
    const float* gbi= gin_b + (long)i*HD;
    const float* ggm= gin_g + (long)i*HD;
    const float* gbe= gin_be + (long)i*HD;
    const float* lg = ln_g + (long)i*HD;
    const float* lb = ln_b + (long)i*HD;
    const float* rW = rw + RESW_OFF + (long)i*HD*HD;
    const float* rb = res_b + (long)i*HD;

    gemm_tc<EPI_BIAS,true><<<gg2,256,SMEM_SZ>>>(cur, Wl, bl, Wr, br, xr,
        nullptr,nullptr,nullptr,nullptr,nullptr,nullptr,nullptr,nullptr,nullptr, xl, HD);
    gat_kernel<<<NN/4, 256>>>((const float4*)xl, (const float4*)xr, ptrGat, colGat, at, gb, alt);
    { float* t = cur; cur = alt; alt = t; }

    ginagg_kernel<<<NN/4, 256>>>((const float4*)cur, ptrGat, colGat, xl);
    gemm_tc<EPI_GIN,false><<<gg1,256,SMEM_SZ>>>(xl, gW, gbi, nullptr,nullptr,nullptr,
        ggm, gbe, nullptr,nullptr,nullptr,nullptr, red + 2*i, nullptr,nullptr, alt, HD);
    { float* t = cur; cur = alt; alt = t; }

    gemm_tc<EPI_RES,false><<<gg1,256,SMEM_SZ>>>(cur, rW, rb, nullptr,nullptr,nullptr,
        nullptr,nullptr, lg, lb, cur, red + 2*i, nullptr,nullptr,nullptr, alt, HD);
    { float* t = cur; cur = alt; alt = t; }
  }

  gemm_tc<EPI_POOL,false><<<gg1,256,SMEM_SZ>>>(cur, rw+POOLW_OFF, pool_b1, nullptr,nullptr,nullptr,
      nullptr,nullptr,nullptr,nullptr,nullptr,nullptr,nullptr, pool_W2, gate, nullptr, HD);
  bsoftmax_kernel<<<1, 1024>>>(gate, batch, pool_b2, gsum);
  emb_kernel<<<NN/8, 256>>>(gate, batch, gsum, cur, emb);

  head_kernel<<<dim3(OO,2), 128>>>(emb, head_W1, head_b1, head_g, head_be, head_W2, (float*)d_out);
}

// round 13
// speedup vs baseline: 1.0185x; 1.0021x over previous
#include <cuda_runtime.h>
#include <stdint.h>
#include <math.h>

#define NN 16000
#define EE 256000
#define EP (EE+NN)
#define DIN 1280
#define HD 256
#define GG 32
#define OO 64

// rounded-weight scratch layout (floats)
#define FPW_OFF   0
#define WL_OFF    327680
#define WR_OFF    458752
#define GINW_OFF  589824
#define RESW_OFF  720896
#define POOLW_OFF 851968
#define RW_TOT    917504

// dynamic smem for gemm: As[3][128][20] + Bs[3][16][264]
#define AS_STRIDE 2560
#define BS_STRIDE 4224
#define AS_FLOATS (3*AS_STRIDE)
#define BS_FLOATS (3*BS_STRIDE)
#define SMEM_SZ ((AS_FLOATS + BS_FLOATS)*4)

// ---------------- device scratch (static, allocation-free) ----------------
__device__ float d_h0[NN*HD];
__device__ float d_h1[NN*HD];
__device__ float d_xl[NN*HD];
__device__ float d_xr[NN*HD];
__device__ float d_rw[RW_TOT];
__device__ int   d_degGat[NN];
__device__ int   d_ptrGat[NN+1];
__device__ int   d_curGat[NN];
__device__ int   d_colGat[EP];
__device__ float d_red[4];
__device__ float d_gate[NN], d_gsum[GG], d_emb[GG*HD];

__device__ __forceinline__ void atomicMaxF(float* addr, float v){
  if (v >= 0.f) atomicMax((int*)addr, __float_as_int(v));
  else          atomicMin((unsigned int*)addr, __float_as_uint(v));
}

__device__ __forceinline__ uint32_t tf32u(float x){
  uint32_t u; asm("cvt.rna.tf32.f32 %0, %1;" : "=r"(u) : "f"(x));
  return u;
}

#define CP16(dst, src) asm volatile("cp.async.cg.shared.global [%0], [%1], 16;\n" :: "r"(dst), "l"(src))
#define CP_COMMIT()    asm volatile("cp.async.commit_group;\n" ::)
template<int N>
__device__ __forceinline__ void cp_wait(){ asm volatile("cp.async.wait_group %0;\n" :: "n"(N)); }

// ---------------- init + weight pre-round (fused) ----------------
__global__ void initro_kernel(int* degGat,float* red,float* emb,float* gate,
                              float* out, const float* __restrict__ head_b2,
                              const float* __restrict__ fpW, const float* __restrict__ wl,
                              const float* __restrict__ wr, const float* __restrict__ ginw,
                              const float* __restrict__ resw, const float* __restrict__ poolw,
                              float* __restrict__ rw){
  int i = blockIdx.x*blockDim.x+threadIdx.x;
  if (i < NN){ degGat[i]=0; gate[i]=0.f; }
  if (i < 4)  red[i]=0.f;
  if (i < GG*HD) emb[i]=0.f;
  if (i < GG*OO) out[i] = head_b2[i % OO];
  for (int idx = i; idx < RW_TOT; idx += gridDim.x*blockDim.x){
    float v; int j = idx;
    if (j < 327680) v = fpW[j];
    else { j -= 327680;
      if (j < 131072) v = wl[j];
      else { j -= 131072;
        if (j < 131072) v = wr[j];
        else { j -= 131072;
          if (j < 131072) v = ginw[j];
          else { j -= 131072;
            if (j < 131072) v = resw[j];
            else v = poolw[j-131072];
          }
        }
      }
    }
    rw[idx] = __uint_as_float(tf32u(v));
  }
}

__global__ void hist_kernel(const int* __restrict__ ei, int* degGat){
  int e = blockIdx.x*blockDim.x+threadIdx.x;
  if (e >= EP) return;
  int d = (e < EE) ? ei[EE+e] : (e-EE);
  atomicAdd(&degGat[d],1);
}

// shuffle-based scan: 1 block, 1024 threads, 16 elems/thread
__global__ void scan_kernel(const int* __restrict__ deg, int* indptr, int* cursor){
  int t = threadIdx.x;
  int lane = t & 31, wid = t >> 5;
  const int CH = 16;
  int st = t*CH;
  int dv[CH];
  int mySum = 0;
  #pragma unroll
  for (int i=0;i<CH;i++){
    int idx = st+i;
    dv[i] = (idx<NN)? deg[idx] : 0;
    mySum += dv[i];
  }
  int inc = mySum;
  #pragma unroll
  for (int off=1; off<32; off<<=1){
    int n = __shfl_up_sync(0xffffffffu, inc, off);
    if (lane >= off) inc += n;
  }
  __shared__ int wtot[32];
  if (lane==31) wtot[wid] = inc;
  __syncthreads();
  if (wid==0){
    int v = wtot[lane];
    #pragma unroll
    for (int off=1; off<32; off<<=1){
      int n = __shfl_up_sync(0xffffffffu, v, off);
      if (lane >= off) v += n;
    }
    wtot[lane] = v;
  }
  __syncthreads();
  int run = inc - mySum + (wid>0 ? wtot[wid-1] : 0);
  #pragma unroll
  for (int i=0;i<CH;i++){
    int idx = st+i;
    if (idx<NN){ indptr[idx]=run; cursor[idx]=run; run+=dv[i]; }
  }
  if (t==1023) indptr[NN] = wtot[31];
}

__global__ void fill_kernel(const int* __restrict__ ei, int* curGat, int* colGat){
  int e = blockIdx.x*blockDim.x+threadIdx.x;
  if (e >= EP) return;
  if (e < EE){
    colGat[atomicAdd(&curGat[ei[EE+e]],1)] = ei[e];
  } else {
    int v = e-EE;
    colGat[atomicAdd(&curGat[v],1)] = v;
  }
}

// --- 128x256-tile tf32 GEMM, 8 warps of 64x64, 3-stage cp.async, fused epi ---
enum { EPI_BIAS=0, EPI_RELU_BN=1, EPI_GIN=2, EPI_RES=3, EPI_POOL=4 };

template<int EPI, bool DUAL>
__global__ __launch_bounds__(256)
void gemm_tc(const float* __restrict__ A,
             const float* __restrict__ B,  const float* __restrict__ bias,
             const float* __restrict__ B2, const float* __restrict__ bias2, float* __restrict__ C2,
             const float* __restrict__ g,   const float* __restrict__ be,
             const float* __restrict__ lng, const float* __restrict__ lnb,
             const float* __restrict__ hres,
             const float* __restrict__ stats, float* __restrict__ statsOut,
             const float* __restrict__ W2pool, float* __restrict__ gatebuf,
             float* __restrict__ C, int K)
{
  extern __shared__ float sm[];
  float* AsP = sm;
  float* BsP = sm + AS_FLOATS;
  int tid = threadIdx.x;
  int lane = tid & 31, w = tid >> 5;
  int warpM = (w >> 2) * 64;
  int warpN = (w & 3) * 64;
  int m0 = blockIdx.x * 128;
  const float* Bp = B; const float* biasp = bias; float* Cp = C;
  if (DUAL && blockIdx.y == 1){ Bp = B2; biasp = bias2; Cp = C2; }
  int tg = lane >> 2, tk = lane & 3;

  float acc[4][8][4];
  #pragma unroll
  for (int i=0;i<4;i++)
    #pragma unroll
    for (int j=0;j<8;j++)
      #pragma unroll
      for (int r=0;r<4;r++) acc[i][j][r]=0.f;

  int rowA  = tid >> 2;
  int k4A   = (tid & 3) * 4;
  int krB = tid >> 4;
  int nbB = (tid & 15)*4;

  uint32_t sA0[3], sA1[3], sB[3];
  #pragma unroll
  for (int s=0;s<3;s++){
    sA0[s] = (uint32_t)__cvta_generic_to_shared(&AsP[s*AS_STRIDE + rowA*20 + k4A]);
    sA1[s] = (uint32_t)__cvta_generic_to_shared(&AsP[s*AS_STRIDE + (rowA+64)*20 + k4A]);
    sB[s]  = (uint32_t)__cvta_generic_to_shared(&BsP[s*BS_STRIDE + krB*264 + nbB]);
  }
  const float* gA0 = A  + (long)(m0+rowA   )*K + k4A;
  const float* gA1 = A  + (long)(m0+rowA+64)*K + k4A;
  const float* gB  = Bp + (long)krB*HD + nbB;

  int nk = K >> 4;
  // prologue: stages 0 and 1
  CP16(sA0[0], gA0); CP16(sA1[0], gA1);
  #pragma unroll
  for (int c4=0;c4<4;c4++) CP16(sB[0] + c4*256, gB + c4*64);
  CP_COMMIT();
  if (nk > 1){
    CP16(sA0[1], gA0+16); CP16(sA1[1], gA1+16);
    const float* gBk = gB + (long)16*HD;
    #pragma unroll
    for (int c4=0;c4<4;c4++) CP16(sB[1] + c4*256, gBk + c4*64);
    CP_COMMIT();
  }

  int st = 0;
  for (int kt=0; kt<nk; kt++){
    if (kt+1 < nk) cp_wait<1>(); else cp_wait<0>();
    __syncthreads();
    if (kt+2 < nk){
      int s2 = st+2; if (s2>=3) s2-=3;
      int kb = (kt+2)<<4;
      CP16(sA0[s2], gA0+kb); CP16(sA1[s2], gA1+kb);
      const float* gBk = gB + (long)kb*HD;
      #pragma unroll
      for (int c4=0;c4<4;c4++) CP16(sB[s2] + c4*256, gBk + c4*64);
      CP_COMMIT();
    }
    const float* Abase = AsP + st*AS_STRIDE;
    const float* Bbase = BsP + st*BS_STRIDE;
    #pragma unroll
    for (int ks=0; ks<2; ks++){
      int k0 = ks*8;
      uint32_t a[4][4], b[8][2];
      #pragma unroll
      for (int i=0;i<4;i++){
        int r = warpM + i*16 + tg;
        a[i][0] = tf32u(Abase[(r  )*20 + k0+tk  ]);
        a[i][1] = tf32u(Abase[(r+8)*20 + k0+tk  ]);
        a[i][2] = tf32u(Abase[(r  )*20 + k0+tk+4]);
        a[i][3] = tf32u(Abase[(r+8)*20 + k0+tk+4]);
      }
      #pragma unroll
      for (int j=0;j<8;j++){
        int c = warpN + j*8 + tg;
        b[j][0] = __float_as_uint(Bbase[(k0+tk  )*264 + c]);
        b[j][1] = __float_as_uint(Bbase[(k0+tk+4)*264 + c]);
      }
      #pragma unroll
      for (int i=0;i<4;i++)
        #pragma unroll
        for (int j=0;j<8;j++)
          asm volatile("mma.sync.aligned.m16n8k8.row.col.f32.tf32.tf32.f32 "
            "{%0,%1,%2,%3}, {%4,%5,%6,%7}, {%8,%9}, {%0,%1,%2,%3};"
            : "+f"(acc[i][j][0]), "+f"(acc[i][j][1]),
              "+f"(acc[i][j][2]), "+f"(acc[i][j][3])
            : "r"(a[i][0]), "r"(a[i][1]), "r"(a[i][2]), "r"(a[i][3]),
              "r"(b[j][0]), "r"(b[j][1]));
    }
    st++; if (st>=3) st-=3;
  }

  // ---- epilogue ----
  const float BNS = rsqrtf(1.0f + 1e-5f);
  float mean=0.f, rdenom=1.f;
  if (EPI==EPI_RES){
    const float inv = 1.0f/((float)NN*(float)HD);
    mean = stats[0]*inv;
    float var = stats[1]*inv - mean*mean;
    rdenom = 1.f/(sqrtf(fmaxf(var,0.f)) + 1e-5f);
  }
  float ssum=0.f, sq=0.f;
  float pgate[4][2];
  if (EPI==EPI_POOL){
    #pragma unroll
    for (int i=0;i<4;i++){ pgate[i][0]=0.f; pgate[i][1]=0.f; }
  }
  #pragma unroll
  for (int j=0;j<8;j++){
    int col = warpN + j*8 + tk*2;
    float b0 = biasp[col], b1 = biasp[col+1];
    float g0=0.f,g1=0.f,e0=0.f,e1=0.f;
    if (EPI==EPI_RELU_BN || EPI==EPI_GIN){
      g0=g[col]*BNS; g1=g[col+1]*BNS; e0=be[col]; e1=be[col+1];
    }
    float lg0=0.f,lg1=0.f,lb0=0.f,lb1=0.f;
    if (EPI==EPI_RES){
      lg0=lng[col]; lg1=lng[col+1]; lb0=lnb[col]; lb1=lnb[col+1];
    }
    float w20=0.f,w21=0.f;
    if (EPI==EPI_POOL){ w20=W2pool[col]; w21=W2pool[col+1]; }
    #pragma unroll
    for (int i=0;i<4;i++){
      #pragma unroll
      for (int h=0;h<2;h++){
        int row = m0 + warpM + i*16 + tg + h*8;
        float v0 = acc[i][j][h*2+0] + b0;
        float v1 = acc[i][j][h*2+1] + b1;
        if (EPI==EPI_RELU_BN){
          v0 = fmaxf(v0,0.f)*g0 + e0;
          v1 = fmaxf(v1,0.f)*g1 + e1;
        } else if (EPI==EPI_GIN){
          v0 = fmaxf(v0,0.f)*g0 + e0; v0 = (v0>0.f)? v0 : 0.2f*v0;
          v1 = fmaxf(v1,0.f)*g1 + e1; v1 = (v1>0.f)? v1 : 0.2f*v1;
          ssum += v0+v1; sq += v0*v0+v1*v1;
        } else if (EPI==EPI_RES){
          float2 hv = *(const float2*)&hres[(long)row*HD + col];
          v0 += (hv.x-mean)*rdenom*lg0 + lb0;
          v1 += (hv.y-mean)*rdenom*lg1 + lb1;
          v0 = (v0>0.f)? v0 : 0.2f*v0;
          v1 = (v1>0.f)? v1 : 0.2f*v1;
        } else if (EPI==EPI_POOL){
          pgate[i][h] += tanhf(v0)*w20 + tanhf(v1)*w21;
        }
        if (EPI!=EPI_POOL)
          *(float2*)&Cp[(long)row*HD + col] = make_float2(v0,v1);
      }
    }
  }
  if (EPI==EPI_GIN){
    #pragma unroll
    for (int off=16; off>0; off>>=1){
      ssum += __shfl_xor_sync(0xffffffffu, ssum, off);
      sq   += __shfl_xor_sync(0xffffffffu, sq,   off);
    }
    if (lane==0){
      atomicAdd(&statsOut[0], ssum);
      atomicAdd(&statsOut[1], sq);
    }
  }
  if (EPI==EPI_POOL){
    #pragma unroll
    for (int i=0;i<4;i++)
      #pragma unroll
      for (int h=0;h<2;h++){
        float p = pgate[i][h];
        p += __shfl_xor_sync(0xffffffffu, p, 1);
        p += __shfl_xor_sync(0xffffffffu, p, 2);
        if (tk==0){
          int row = m0 + warpM + i*16 + tg + h*8;
          atomicAdd(&gatebuf[row], p);
        }
      }
  }
}

// ------- GATv2: 4 warps/node = (edge-half x feature-half), float4 lanes -------
// Each warp owns 128 channels (4 heads). A head's 32 channels = one 8-lane group,
// so logit reduction is shfl 1,2,4. Edge-halves combined through smem.
__global__ __launch_bounds__(256)
void gat_kernel(const float4* __restrict__ xl4, const float4* __restrict__ xr4,
                const int* __restrict__ indptr, const int* __restrict__ col,
                const float* __restrict__ att, const float* __restrict__ gbias,
                float* __restrict__ hout){
  __shared__ float part[2][2][32][5];
  int warpid = threadIdx.x >> 5;
  int lane = threadIdx.x & 31;
  int nib = warpid >> 2;        // node within block: 0..1
  int sub = warpid & 3;
  int eHalf = sub >> 1;
  int fHalf = sub & 1;
  int w = blockIdx.x*2 + nib;   // grid = NN/2, exact
  int fbase = fHalf*32 + lane;  // float4 index within a node's 64-quad row
  const float4* at4 = (const float4*)att;
  float4 a  = at4[fbase];
  float4 xr = xr4[w*64 + fbase];
  float4 acc = make_float4(0,0,0,0);
  float s = 0.f;
  int p0 = indptr[w], p1 = indptr[w+1];
  int mid = p0 + ((p1-p0)+1)/2;
  int jb = eHalf ? mid : p0;
  int je = eHalf ? p1  : mid;
  int j = jb;
  for (; j+1 < je; j += 2){
    int ua = col[j], ub = col[j+1];
    float4 xa = xl4[ua*64 + fbase];
    float4 xb = xl4[ub*64 + fbase];
    float qa, qb, v;
    v = xa.x+xr.x; v = v>0.f?v:0.2f*v; qa  = v*a.x;
    v = xa.y+xr.y; v = v>0.f?v:0.2f*v; qa += v*a.y;
    v = xa.z+xr.z; v = v>0.f?v:0.2f*v; qa += v*a.z;
    v = xa.w+xr.w; v = v>0.f?v:0.2f*v; qa += v*a.w;
    v = xb.x+xr.x; v = v>0.f?v:0.2f*v; qb  = v*a.x;
    v = xb.y+xr.y; v = v>0.f?v:0.2f*v; qb += v*a.y;
    v = xb.z+xr.z; v = v>0.f?v:0.2f*v; qb += v*a.z;
    v = xb.w+xr.w; v = v>0.f?v:0.2f*v; qb += v*a.w;
    qa += __shfl_xor_sync(0xffffffffu,qa,1);
    qb += __shfl_xor_sync(0xffffffffu,qb,1);
    qa += __shfl_xor_sync(0xffffffffu,qa,2);
    qb += __shfl_xor_sync(0xffffffffu,qb,2);
    qa += __shfl_xor_sync(0xffffffffu,qa,4);
    qb += __shfl_xor_sync(0xffffffffu,qb,4);
    float ca = __expf(qa), cb = __expf(qb);
    s += ca;
    acc.x += ca*xa.x; acc.y += ca*xa.y; acc.z += ca*xa.z; acc.w += ca*xa.w;
    s += cb;
    acc.x += cb*xb.x; acc.y += cb*xb.y; acc.z += cb*xb.z; acc.w += cb*xb.w;
  }
  if (j < je){
    int u = col[j];
    float4 x = xl4[u*64 + fbase];
    float q, v;
    v = x.x+xr.x; v = v>0.f?v:0.2f*v; q  = v*a.x;
    v = x.y+xr.y; v = v>0.f?v:0.2f*v; q += v*a.y;
    v = x.z+xr.z; v = v>0.f?v:0.2f*v; q += v*a.z;
    v = x.w+xr.w; v = v>0.f?v:0.2f*v; q += v*a.w;
    q += __shfl_xor_sync(0xffffffffu,q,1);
    q += __shfl_xor_sync(0xffffffffu,q,2);
    q += __shfl_xor_sync(0xffffffffu,q,4);
    float c = __expf(q);
    s += c;
    acc.x += c*x.x; acc.y += c*x.y; acc.z += c*x.z; acc.w += c*x.w;
  }
  if (eHalf == 1){
    part[nib][fHalf][lane][0] = acc.x;
    part[nib][fHalf][lane][1] = acc.y;
    part[nib][fHalf][lane][2] = acc.z;
    part[nib][fHalf][lane][3] = acc.w;
    part[nib][fHalf][lane][4] = s;
  }
  __syncthreads();
  if (eHalf == 0){
    acc.x += part[nib][fHalf][lane][0];
    acc.y += part[nib][fHalf][lane][1];
    acc.z += part[nib][fHalf][lane][2];
    acc.w += part[nib][fHalf][lane][3];
    s     += part[nib][fHalf][lane][4];
    float r = 1.f/(s+1e-16f);
    float4 b = ((const float4*)gbias)[fbase];
    float4 o;
    o.x = acc.x*r + b.x; o.y = acc.y*r + b.y;
    o.z = acc.z*r + b.z; o.w = acc.w*r + b.w;
    ((float4*)hout)[w*64 + fbase] = o;
  }
}

// ---- GIN aggregation via GAT CSR (self-loop in list), 4 warps/node ----
__global__ __launch_bounds__(256)
void ginagg_kernel(const float4* __restrict__ h4, const int* __restrict__ indptr,
                   const int* __restrict__ col, float* __restrict__ tmp){
  __shared__ float part[2][2][32][4];
  int warpid = threadIdx.x >> 5;
  int lane = threadIdx.x & 31;
  int nib = warpid >> 2;
  int sub = warpid & 3;
  int eHalf = sub >> 1;
  int fHalf = sub & 1;
  int w = blockIdx.x*2 + nib;
  int fbase = fHalf*32 + lane;
  float4 acc = make_float4(0,0,0,0);
  int p0 = indptr[w], p1 = indptr[w+1];
  int mid = p0 + ((p1-p0)+1)/2;
  int jb = eHalf ? mid : p0;
  int je = eHalf ? p1  : mid;
  int j = jb;
  for (; j+3 < je; j += 4){
    int u0 = col[j], u1 = col[j+1], u2 = col[j+2], u3 = col[j+3];
    float4 x0 = h4[u0*64 + fbase];
    float4 x1 = h4[u1*64 + fbase];
    float4 x2 = h4[u2*64 + fbase];
    float4 x3 = h4[u3*64 + fbase];
    acc.x+=x0.x; acc.y+=x0.y; acc.z+=x0.z; acc.w+=x0.w;
    acc.x+=x1.x; acc.y+=x1.y; acc.z+=x1.z; acc.w+=x1.w;
    acc.x+=x2.x; acc.y+=x2.y; acc.z+=x2.z; acc.w+=x2.w;
    acc.x+=x3.x; acc.y+=x3.y; acc.z+=x3.z; acc.w+=x3.w;
  }
  for (; j < je; j++){
    int u = col[j];
    float4 x = h4[u*64 + fbase];
    acc.x+=x.x; acc.y+=x.y; acc.z+=x.z; acc.w+=x.w;
  }
  if (eHalf == 1){
    part[nib][fHalf][lane][0]=acc.x;
    part[nib][fHalf][lane][1]=acc.y;
    part[nib][fHalf][lane][2]=acc.z;
    part[nib][fHalf][lane][3]=acc.w;
  }
  __syncthreads();
  if (eHalf == 0){
    acc.x+=part[nib][fHalf][lane][0];
    acc.y+=part[nib][fHalf][lane][1];
    acc.z+=part[nib][fHalf][lane][2];
    acc.w+=part[nib][fHalf][lane][3];
    ((float4*)tmp)[w*64 + fbase] = acc;
  }
}

// ---------------- pooling: batch softmax (single block) ----------------
__global__ void bsoftmax_kernel(float* __restrict__ gate, const int* __restrict__ batch,
                                const float* __restrict__ b2, float* __restrict__ gsum){
  __shared__ float smax[GG], ssum[GG];
  int t = threadIdx.x;  // 1024 threads
  if (t < GG){ smax[t] = -1e30f; ssum[t] = 0.f; }
  __syncthreads();
  float b2v = b2[0];
  for (int v=t; v<NN; v+=1024)
    atomicMaxF(&smax[batch[v]], gate[v]+b2v);
  __syncthreads();
  for (int v=t; v<NN; v+=1024){
    int b = batch[v];
    float e = __expf(gate[v]+b2v - smax[b]);
    gate[v] = e;
    atomicAdd(&ssum[b], e);
  }
  __syncthreads();
  if (t < GG) gsum[t] = ssum[t];
}

__global__ __launch_bounds__(256)
void emb_kernel(const float* __restrict__ gate, const int* __restrict__ batch,
                const float* __restrict__ gsum, const float* __restrict__ h, float* __restrict__ emb){
  int w = (blockIdx.x*blockDim.x + threadIdx.x)>>5;
  int lane = threadIdx.x & 31;
  if (w >= NN) return;
  int b = batch[w];
  float c = gate[w]/(gsum[b]+1e-16f);
  #pragma unroll
  for (int k=0;k<8;k++) atomicAdd(&emb[b*HD + k*32 + lane], c*h[w*HD + k*32 + lane]);
}

// ---------------- label heads: grid (OO,2), 128 thr, hidden-split ----------------
__global__ __launch_bounds__(128)
void head_kernel(const float* __restrict__ emb, const float* __restrict__ W1,
                 const float* __restrict__ b1, const float* __restrict__ g,
                 const float* __restrict__ be, const float* __restrict__ W2,
                 float* __restrict__ out){
  __shared__ float embS[GG*HD];
  __shared__ float sred[GG];
  int o = blockIdx.x;
  int half = blockIdx.y;
  int t = threadIdx.x;
  int hu = half*128 + t;
  for (int i=t;i<GG*HD;i+=128) embS[i]=emb[i];
  if (t < GG) sred[t]=0.f;
  __syncthreads();
  float acc[GG];
  #pragma unroll
  for (int b=0;b<GG;b++) acc[b]=0.f;
  const float* w = W1 + (long)o*HD*256 + hu;
  for (int d=0;d<HD;d++){
    float wv = w[(long)d*256];
    #pragma unroll
    for (int b=0;b<GG;b++) acc[b] += embS[b*HD+d]*wv;
  }
  const float BNS = rsqrtf(1.0f + 1e-5f);
  float bnscale = g[o*256+hu]*BNS;
  float beta = be[o*256+hu];
  float bb1 = b1[o*256+hu];
  float w2 = W2[o*256+hu];
  #pragma unroll
  for (int b=0;b<GG;b++){
    float z = acc[b]+bb1;
    float sv = z/(1.f+__expf(-z));
    float bnv = sv*bnscale + beta;
    atomicAdd(&sred[b], bnv*w2);
  }
  __syncthreads();
  if (t < GG) atomicAdd(&out[t*OO + o], sred[t]);
}

// ---------------- host launch ----------------
extern "C" void kernel_launch(void* const* d_in, const int* in_sizes, int n_in,
                              void* d_out, int out_size) {
  (void)in_sizes; (void)n_in; (void)out_size;
  const float* x      = (const float*)d_in[0];
  const int*   ei     = (const int*)  d_in[1];
  const int*   batch  = (const int*)  d_in[2];
  const float* fp_W   = (const float*)d_in[3];
  const float* fp_b   = (const float*)d_in[4];
  const float* fp_g   = (const float*)d_in[5];
  const float* fp_be  = (const float*)d_in[6];
  const float* gat_Wl = (const float*)d_in[7];
  const float* gat_bl = (const float*)d_in[8];
  const float* gat_Wr = (const float*)d_in[9];
  const float* gat_br = (const float*)d_in[10];
  const float* gat_att= (const float*)d_in[11];
  const float* gat_bias=(const float*)d_in[12];
  const float* gin_W  = (const float*)d_in[13];
  const float* gin_b  = (const float*)d_in[14];
  const float* gin_g  = (const float*)d_in[15];
  const float* gin_be = (const float*)d_in[16];
  const float* ln_g   = (const float*)d_in[17];
  const float* ln_b   = (const float*)d_in[18];
  const float* res_W  = (const float*)d_in[19];
  const float* res_b  = (const float*)d_in[20];
  const float* pool_W1= (const float*)d_in[21];
  const float* pool_b1= (const float*)d_in[22];
  const float* pool_W2= (const float*)d_in[23];
  const float* pool_b2= (const float*)d_in[24];
  const float* head_W1= (const float*)d_in[25];
  const float* head_b1= (const float*)d_in[26];
  const float* head_g = (const float*)d_in[27];
  const float* head_be= (const float*)d_in[28];
  const float* head_W2= (const float*)d_in[29];
  const float* head_b2= (const float*)d_in[30];

  float *h0,*h1,*xl,*xr,*rw,*red,*gate,*gsum,*emb;
  int *degGat,*ptrGat,*curGat,*colGat;
  cudaGetSymbolAddress((void**)&h0, d_h0);
  cudaGetSymbolAddress((void**)&h1, d_h1);
  cudaGetSymbolAddress((void**)&xl, d_xl);
  cudaGetSymbolAddress((void**)&xr, d_xr);
  cudaGetSymbolAddress((void**)&rw, d_rw);
  cudaGetSymbolAddress((void**)&red, d_red);
  cudaGetSymbolAddress((void**)&gate, d_gate);
  cudaGetSymbolAddress((void**)&gsum, d_gsum);
  cudaGetSymbolAddress((void**)&emb, d_emb);
  cudaGetSymbolAddress((void**)&degGat, d_degGat);
  cudaGetSymbolAddress((void**)&ptrGat, d_ptrGat);
  cudaGetSymbolAddress((void**)&curGat, d_curGat);
  cudaGetSymbolAddress((void**)&colGat, d_colGat);

  cudaFuncSetAttribute(gemm_tc<EPI_RELU_BN,false>, cudaFuncAttributeMaxDynamicSharedMemorySize, SMEM_SZ);
  cudaFuncSetAttribute(gemm_tc<EPI_BIAS,true>,     cudaFuncAttributeMaxDynamicSharedMemorySize, SMEM_SZ);
  cudaFuncSetAttribute(gemm_tc<EPI_GIN,false>,     cudaFuncAttributeMaxDynamicSharedMemorySize, SMEM_SZ);
  cudaFuncSetAttribute(gemm_tc<EPI_RES,false>,     cudaFuncAttributeMaxDynamicSharedMemorySize, SMEM_SZ);
  cudaFuncSetAttribute(gemm_tc<EPI_POOL,false>,    cudaFuncAttributeMaxDynamicSharedMemorySize, SMEM_SZ);

  dim3 gg1(NN/128, 1);
  dim3 gg2(NN/128, 2);

  initro_kernel<<<896, 256>>>(degGat, red, emb, gate, (float*)d_out, head_b2,
                              fp_W, gat_Wl, gat_Wr, gin_W, res_W, pool_W1, rw);
  hist_kernel<<<(EP+255)/256, 256>>>(ei, degGat);
  scan_kernel<<<1, 1024>>>(degGat, ptrGat, curGat);
  // feature projection: h0 = bn(relu(x @ fp_W + fp_b))   <-- ncu capture target (#4)
  gemm_tc<EPI_RELU_BN,false><<<gg1,256,SMEM_SZ>>>(x, rw+FPW_OFF, fp_b, nullptr,nullptr,nullptr,
      fp_g, fp_be, nullptr,nullptr,nullptr,nullptr,nullptr,nullptr,nullptr, h0, DIN);
  fill_kernel<<<(EP+255)/256, 256>>>(ei, curGat, colGat);

  float* cur = h0;
  float* alt = h1;
  for (int i=0;i<2;i++){
    const float* Wl = rw + WL_OFF + (long)i*HD*HD;
    const float* bl = gat_bl + (long)i*HD;
    const float* Wr = rw + WR_OFF + (long)i*HD*HD;
    const float* br = gat_br + (long)i*HD;
    const float* at = gat_att + (long)i*8*32;
    const float* gb = gat_bias + (long)i*HD;
    const float* gW = rw + GINW_OFF + (long)i*HD*HD;
    const float* gbi= gin_b + (long)i*HD;
    const float* ggm= gin_g + (long)i*HD;
    const float* gbe= gin_be + (long)i*HD;
    const float* lg = ln_g + (long)i*HD;
    const float* lb = ln_b + (long)i*HD;
    const float* rW = rw + RESW_OFF + (long)i*HD*HD;
    const float* rb = res_b + (long)i*HD;

    gemm_tc<EPI_BIAS,true><<<gg2,256,SMEM_SZ>>>(cur, Wl, bl, Wr, br, xr,
        nullptr,nullptr,nullptr,nullptr,nullptr,nullptr,nullptr,nullptr,nullptr, xl, HD);
    gat_kernel<<<NN/2, 256>>>((const float4*)xl, (const float4*)xr, ptrGat, colGat, at, gb, alt);
    { float* t = cur; cur = alt; alt = t; }

    ginagg_kernel<<<NN/2, 256>>>((const float4*)cur, ptrGat, colGat, xl);
    gemm_tc<EPI_GIN,false><<<gg1,256,SMEM_SZ>>>(xl, gW, gbi, nullptr,nullptr,nullptr,
        ggm, gbe, nullptr,nullptr,nullptr,nullptr, red + 2*i, nullptr,nullptr, alt, HD);
    { float* t = cur; cur = alt; alt = t; }

    gemm_tc<EPI_RES,false><<<gg1,256,SMEM_SZ>>>(cur, rW, rb, nullptr,nullptr,nullptr,
        nullptr,nullptr, lg, lb, cur, red + 2*i, nullptr,nullptr,nullptr, alt, HD);
    { float* t = cur; cur = alt; alt = t; }
  }

  gemm_tc<EPI_POOL,false><<<gg1,256,SMEM_SZ>>>(cur, rw+POOLW_OFF, pool_b1, nullptr,nullptr,nullptr,
      nullptr,nullptr,nullptr,nullptr,nullptr,nullptr,nullptr, pool_W2, gate, nullptr, HD);
  bsoftmax_kernel<<<1, 1024>>>(gate, batch, pool_b2, gsum);
  emb_kernel<<<NN/8, 256>>>(gate, batch, gsum, cur, emb);

  head_kernel<<<dim3(OO,2), 128>>>(emb, head_W1, head_b1, head_g, head_be, head_W2, (float*)d_out);
}